// round 1
// baseline (speedup 1.0000x reference)
#include <cuda_runtime.h>
#include <math.h>
#include <stdint.h>

// Problem constants
#define D    1024
#define F    513          // rfft bins
#define FP   520          // padded F (multiple of 8)
#define N2   (2*FP)       // stacked re/im planes = 1040
#define BB   2
#define TT   2048
#define M4   (BB*TT)      // 4096
#define CC   10
#define NCH  64           // scan chunks
#define CL   (TT/NCH)     // 32

// ---------------- static device scratch (no allocs allowed) ----------------
__device__ float g_TW [(size_t)N2*D];       // twiddle rows: [0..512]=cos, [FP..FP+512]=-sin, pads=0
__device__ float g_WT0[(size_t)D*D];        // Wq^T
__device__ float g_WT1[(size_t)D*D];        // Wk^T
__device__ float g_WT2[(size_t)D*D];        // Wv^T
__device__ float g_WF0[(size_t)N2*D];       // TW @ Wq   (rows f', cols e)
__device__ float g_WF1[(size_t)N2*D];
__device__ float g_WF2[(size_t)N2*D];
__device__ float g_Gt [(size_t)D*N2];       // Wo @ TW^T (rows e, cols f')
__device__ float g_FQ [(size_t)M4*N2];      // fq planes: row m, cols [0..F)=re, [FP..FP+F)=im
__device__ float g_FK [(size_t)M4*N2];
__device__ float g_FV [(size_t)M4*N2];
__device__ float g_Sre[(size_t)BB*NCH*CC*FP];
__device__ float g_Sim[(size_t)BB*NCH*CC*FP];
__device__ float g_RS [(size_t)M4*N2];      // scaled r planes

// ---------------- twiddle builder ----------------
__global__ void build_tw() {
    int d = blockIdx.x * blockDim.x + threadIdx.x;
    int n = blockIdx.y;
    if (d >= D) return;
    int f = (n < FP) ? n : n - FP;
    float v = 0.f;
    if (f < F) {
        int idx = (f * d) & (D - 1);                 // exact argument reduction
        double ang = (double)idx * (6.283185307179586476925286766559 / (double)D);
        v = (n < FP) ? (float)cos(ang) : (float)(-sin(ang));
    }
    g_TW[(size_t)n * D + d] = v;
}

// ---------------- 1024x1024 transpose ----------------
__global__ void transpose_k(const float* __restrict__ A, float* __restrict__ AT) {
    __shared__ float tile[32][33];
    int x  = blockIdx.x * 32 + threadIdx.x;
    int y0 = blockIdx.y * 32 + threadIdx.y;
    #pragma unroll
    for (int i = 0; i < 32; i += 8)
        tile[threadIdx.y + i][threadIdx.x] = A[(size_t)(y0 + i) * D + x];
    __syncthreads();
    int x2 = blockIdx.y * 32 + threadIdx.x;
    int y2 = blockIdx.x * 32 + threadIdx.y;
    #pragma unroll
    for (int i = 0; i < 32; i += 8)
        AT[(size_t)(y2 + i) * D + x2] = tile[threadIdx.x][threadIdx.y + i];
}

// ---------------- generic NT GEMM: C[m,n] = sum_k A[m,k]*B[n,k] ----------------
// A row-major [M,K], B row-major [N,K], C row-major [M,N]. K % 16 == 0, K % 4 == 0.
__global__ __launch_bounds__(256) void gemm_nt(const float* __restrict__ A,
                                               const float* __restrict__ Bm,
                                               float* __restrict__ Cm,
                                               int M, int N, int K) {
    __shared__ float As[16][132];
    __shared__ float Bs[16][132];
    const int tid   = threadIdx.x;
    const int lr    = tid >> 2;          // 0..63
    const int lc    = (tid & 3) << 2;    // 0,4,8,12
    const int tx    = tid & 15;
    const int ty    = tid >> 4;
    const int mBase = blockIdx.y * 128;
    const int nBase = blockIdx.x * 128;

    float acc[8][8];
    #pragma unroll
    for (int i = 0; i < 8; i++)
        #pragma unroll
        for (int j = 0; j < 8; j++) acc[i][j] = 0.f;

    for (int k0 = 0; k0 < K; k0 += 16) {
        #pragma unroll
        for (int r = 0; r < 2; r++) {
            int arow = mBase + lr + r * 64;
            float4 va = make_float4(0.f, 0.f, 0.f, 0.f);
            if (arow < M)
                va = *reinterpret_cast<const float4*>(A + (size_t)arow * K + k0 + lc);
            As[lc + 0][lr + r * 64] = va.x;
            As[lc + 1][lr + r * 64] = va.y;
            As[lc + 2][lr + r * 64] = va.z;
            As[lc + 3][lr + r * 64] = va.w;

            int brow = nBase + lr + r * 64;
            float4 vb = make_float4(0.f, 0.f, 0.f, 0.f);
            if (brow < N)
                vb = *reinterpret_cast<const float4*>(Bm + (size_t)brow * K + k0 + lc);
            Bs[lc + 0][lr + r * 64] = vb.x;
            Bs[lc + 1][lr + r * 64] = vb.y;
            Bs[lc + 2][lr + r * 64] = vb.z;
            Bs[lc + 3][lr + r * 64] = vb.w;
        }
        __syncthreads();

        #pragma unroll
        for (int k = 0; k < 16; k++) {
            float a[8], b[8];
            *reinterpret_cast<float4*>(&a[0]) = *reinterpret_cast<float4*>(&As[k][ty * 8]);
            *reinterpret_cast<float4*>(&a[4]) = *reinterpret_cast<float4*>(&As[k][ty * 8 + 4]);
            *reinterpret_cast<float4*>(&b[0]) = *reinterpret_cast<float4*>(&Bs[k][tx * 8]);
            *reinterpret_cast<float4*>(&b[4]) = *reinterpret_cast<float4*>(&Bs[k][tx * 8 + 4]);
            #pragma unroll
            for (int i = 0; i < 8; i++)
                #pragma unroll
                for (int j = 0; j < 8; j++)
                    acc[i][j] = fmaf(a[i], b[j], acc[i][j]);
        }
        __syncthreads();
    }

    #pragma unroll
    for (int i = 0; i < 8; i++) {
        int row = mBase + ty * 8 + i;
        if (row < M) {
            #pragma unroll
            for (int j = 0; j < 8; j++) {
                int col = nBase + tx * 8 + j;
                if (col < N) Cm[(size_t)row * N + col] = acc[i][j];
            }
        }
    }
}

// ---------------- scan pass 1: per-chunk partial sums of fk[perm]*fv ----------------
__global__ __launch_bounds__(544) void scan_partial(const int* __restrict__ perms) {
    __shared__ float skr[F], ski[F];
    const int b = blockIdx.y, ch = blockIdx.x;
    const int tid = threadIdx.x;
    const int f = tid;
    int   g[CC];
    float ar[CC], ai[CC];
    if (f < F) {
        #pragma unroll
        for (int c = 0; c < CC; c++) { g[c] = perms[c * F + f]; ar[c] = 0.f; ai[c] = 0.f; }
    }
    const int t0 = ch * CL;
    for (int t = t0; t < t0 + CL; t++) {
        const size_t row = (size_t)(b * TT + t) * N2;
        for (int i = tid; i < F; i += blockDim.x) {
            skr[i] = g_FK[row + i];
            ski[i] = g_FK[row + FP + i];
        }
        __syncthreads();
        if (f < F) {
            float vr = g_FV[row + f], vi = g_FV[row + FP + f];
            #pragma unroll
            for (int c = 0; c < CC; c++) {
                float kr = skr[g[c]], ki = ski[g[c]];
                ar[c] = fmaf(kr, vr, fmaf(-ki, vi, ar[c]));
                ai[c] = fmaf(kr, vi, fmaf( ki, vr, ai[c]));
            }
        }
        __syncthreads();
    }
    if (f < F) {
        size_t base = (size_t)(b * NCH + ch) * CC * FP + f;
        #pragma unroll
        for (int c = 0; c < CC; c++) {
            g_Sre[base + (size_t)c * FP] = ar[c];
            g_Sim[base + (size_t)c * FP] = ai[c];
        }
    }
}

// ---------------- scan pass 2: in-place exclusive scan over chunks ----------------
__global__ void scan_offsets() {
    int idx = blockIdx.x * blockDim.x + threadIdx.x;   // over B*C*FP
    if (idx >= BB * CC * FP) return;
    int f = idx % FP;
    int c = (idx / FP) % CC;
    int b = idx / (FP * CC);
    float rr = 0.f, ri = 0.f;
    for (int ch = 0; ch < NCH; ch++) {
        size_t off = ((size_t)(b * NCH + ch) * CC + c) * FP + f;
        float vr = g_Sre[off], vi = g_Sim[off];
        g_Sre[off] = rr; g_Sim[off] = ri;
        rr += vr; ri += vi;
    }
}

// ---------------- scan pass 3: replay + unbind, write scaled r planes ----------------
__global__ __launch_bounds__(544) void scan_final(const int* __restrict__ perms) {
    __shared__ float skr[F], ski[F], sqr[F], sqi[F];
    const int b = blockIdx.y, ch = blockIdx.x;
    const int tid = threadIdx.x;
    const int f = tid;
    int   g[CC];
    float ar[CC], ai[CC];
    float s = 0.f;
    if (f < F) {
        size_t base = (size_t)(b * NCH + ch) * CC * FP + f;
        #pragma unroll
        for (int c = 0; c < CC; c++) {
            g[c]  = perms[c * F + f];
            ar[c] = g_Sre[base + (size_t)c * FP];
            ai[c] = g_Sim[base + (size_t)c * FP];
        }
        s = ((f == 0 || f == F - 1) ? 1.f : 2.f) / ((float)CC * (float)D);
    }
    const int t0 = ch * CL;
    for (int t = t0; t < t0 + CL; t++) {
        const size_t row = (size_t)(b * TT + t) * N2;
        for (int i = tid; i < F; i += blockDim.x) {
            skr[i] = g_FK[row + i];
            ski[i] = g_FK[row + FP + i];
            sqr[i] = g_FQ[row + i];
            sqi[i] = g_FQ[row + FP + i];
        }
        __syncthreads();
        if (f < F) {
            float vr = g_FV[row + f], vi = g_FV[row + FP + f];
            float rr = 0.f, ri = 0.f;
            #pragma unroll
            for (int c = 0; c < CC; c++) {
                float kr = skr[g[c]], ki = ski[g[c]];
                ar[c] = fmaf(kr, vr, fmaf(-ki, vi, ar[c]));
                ai[c] = fmaf(kr, vi, fmaf( ki, vr, ai[c]));
                float qr = sqr[g[c]], qi = sqi[g[c]];
                rr = fmaf(qr, ar[c], fmaf( qi, ai[c], rr));   // re(conj(q)*acc)
                ri = fmaf(qr, ai[c], fmaf(-qi, ar[c], ri));   // im(conj(q)*acc)
            }
            g_RS[row + f]      = rr * s;
            g_RS[row + FP + f] = ri * s;
        } else if (f < FP) {
            // zero pad columns so the output GEMM can sum over all K=2*FP
            g_RS[row + f]      = 0.f;
            g_RS[row + FP + f] = 0.f;
        }
        __syncthreads();
    }
}

// ---------------- host launcher ----------------
extern "C" void kernel_launch(void* const* d_in, const int* in_sizes, int n_in,
                              void* d_out, int out_size) {
    (void)in_sizes; (void)n_in; (void)out_size;
    const float* x     = (const float*)d_in[0];
    const float* Wq    = (const float*)d_in[1];
    const float* Wk    = (const float*)d_in[2];
    const float* Wv    = (const float*)d_in[3];
    const float* Wo    = (const float*)d_in[4];
    const int*   perms = (const int*)  d_in[5];
    float* out = (float*)d_out;

    float *pTW, *pWT0, *pWT1, *pWT2, *pWF0, *pWF1, *pWF2, *pGt, *pFQ, *pFK, *pFV, *pRS;
    cudaGetSymbolAddress((void**)&pTW,  g_TW);
    cudaGetSymbolAddress((void**)&pWT0, g_WT0);
    cudaGetSymbolAddress((void**)&pWT1, g_WT1);
    cudaGetSymbolAddress((void**)&pWT2, g_WT2);
    cudaGetSymbolAddress((void**)&pWF0, g_WF0);
    cudaGetSymbolAddress((void**)&pWF1, g_WF1);
    cudaGetSymbolAddress((void**)&pWF2, g_WF2);
    cudaGetSymbolAddress((void**)&pGt,  g_Gt);
    cudaGetSymbolAddress((void**)&pFQ,  g_FQ);
    cudaGetSymbolAddress((void**)&pFK,  g_FK);
    cudaGetSymbolAddress((void**)&pFV,  g_FV);
    cudaGetSymbolAddress((void**)&pRS,  g_RS);

    // 1. twiddles
    build_tw<<<dim3(D / 256, N2), 256>>>();

    // 2. weight transposes
    transpose_k<<<dim3(32, 32), dim3(32, 8)>>>(Wq, pWT0);
    transpose_k<<<dim3(32, 32), dim3(32, 8)>>>(Wk, pWT1);
    transpose_k<<<dim3(32, 32), dim3(32, 8)>>>(Wv, pWT2);

    // 3. fused DFT weights: WF = NT(TW[N2,D], W^T[D,D])  -> [N2, D]
    gemm_nt<<<dim3(8, 9), 256>>>(pTW, pWT0, pWF0, N2, D, D);
    gemm_nt<<<dim3(8, 9), 256>>>(pTW, pWT1, pWF1, N2, D, D);
    gemm_nt<<<dim3(8, 9), 256>>>(pTW, pWT2, pWF2, N2, D, D);

    // 4. output-side fused weights: Gt = NT(Wo[D,D], TW[N2,D]) -> [D, N2]
    gemm_nt<<<dim3(9, 8), 256>>>(Wo, pTW, pGt, D, N2, D);

    // 5. projections fused with rfft: f* = NT(x[M4,D], WF[N2,D]) -> [M4, N2]
    gemm_nt<<<dim3(9, 32), 256>>>(x, pWF0, pFQ, M4, N2, D);
    gemm_nt<<<dim3(9, 32), 256>>>(x, pWF1, pFK, M4, N2, D);
    gemm_nt<<<dim3(9, 32), 256>>>(x, pWF2, pFV, M4, N2, D);

    // 6. causal cumulative bind/unbind (chunked scan over T)
    scan_partial<<<dim3(NCH, BB), 544>>>(perms);
    scan_offsets<<<(BB * CC * FP + 255) / 256, 256>>>();
    scan_final  <<<dim3(NCH, BB), 544>>>(perms);

    // 7. irfft + output projection fused: out = NT(RS[M4,N2], Gt[D,N2]) -> [M4, D]
    gemm_nt<<<dim3(8, 32), 256>>>(pRS, pGt, out, M4, D, N2);
}

// round 3
// speedup vs baseline: 1.8217x; 1.8217x over previous
#include <cuda_runtime.h>
#include <cuda_bf16.h>
#include <math.h>
#include <stdint.h>

// Problem constants
#define D    1024
#define F    513          // rfft bins
#define FP   576          // padded F (N2 = 1152 = 9*128; every GEMM dim % 128 == 0)
#define N2   (2*FP)       // 1152: [0..F) = re, [FP..FP+F) = im, pads zero
#define BB   2
#define TT   2048
#define M4   (BB*TT)      // 4096
#define CC   10
#define NCH  64
#define CL   (TT/NCH)     // 32

// ======================= static device scratch =======================
__device__ float g_TW [(size_t)N2*D];
__device__ float g_WT0[(size_t)D*D];
__device__ float g_WT1[(size_t)D*D];
__device__ float g_WT2[(size_t)D*D];
__device__ float g_WF0[(size_t)N2*D];
__device__ float g_WF1[(size_t)N2*D];
__device__ float g_WF2[(size_t)N2*D];
__device__ float g_Gt [(size_t)D*N2];
__device__ float g_FQ [(size_t)M4*N2];
__device__ float g_FK [(size_t)M4*N2];
__device__ float g_FV [(size_t)M4*N2];
__device__ float g_Sre[(size_t)BB*NCH*CC*FP];
__device__ float g_Sim[(size_t)BB*NCH*CC*FP];
__device__ float g_RS [(size_t)M4*N2];
// bf16 split buffers (hi, lo)
__device__ __nv_bfloat16 g_TWh[(size_t)N2*D],  g_TWl[(size_t)N2*D];
__device__ __nv_bfloat16 g_W0h[(size_t)D*D],   g_W0l[(size_t)D*D];
__device__ __nv_bfloat16 g_W1h[(size_t)D*D],   g_W1l[(size_t)D*D];
__device__ __nv_bfloat16 g_W2h[(size_t)D*D],   g_W2l[(size_t)D*D];
__device__ __nv_bfloat16 g_Woh[(size_t)D*D],   g_Wol[(size_t)D*D];
__device__ __nv_bfloat16 g_F0h[(size_t)N2*D],  g_F0l[(size_t)N2*D];
__device__ __nv_bfloat16 g_F1h[(size_t)N2*D],  g_F1l[(size_t)N2*D];
__device__ __nv_bfloat16 g_F2h[(size_t)N2*D],  g_F2l[(size_t)N2*D];
__device__ __nv_bfloat16 g_Gth[(size_t)D*N2],  g_Gtl[(size_t)D*N2];
__device__ __nv_bfloat16 g_Xh [(size_t)M4*D],  g_Xl [(size_t)M4*D];
__device__ __nv_bfloat16 g_Rh [(size_t)M4*N2], g_Rl [(size_t)M4*N2];

// ======================= small kernels =======================
__global__ void build_tw() {
    int d = blockIdx.x * blockDim.x + threadIdx.x;
    int n = blockIdx.y;
    if (d >= D) return;
    int f = (n < FP) ? n : n - FP;
    float v = 0.f;
    if (f < F) {
        int idx = (f * d) & (D - 1);
        double ang = (double)idx * (6.283185307179586476925286766559 / (double)D);
        v = (n < FP) ? (float)cos(ang) : (float)(-sin(ang));
    }
    g_TW[(size_t)n * D + d] = v;
}

__global__ void transpose_k(const float* __restrict__ A, float* __restrict__ AT) {
    __shared__ float tile[32][33];
    int x  = blockIdx.x * 32 + threadIdx.x;
    int y0 = blockIdx.y * 32 + threadIdx.y;
    #pragma unroll
    for (int i = 0; i < 32; i += 8)
        tile[threadIdx.y + i][threadIdx.x] = A[(size_t)(y0 + i) * D + x];
    __syncthreads();
    int x2 = blockIdx.y * 32 + threadIdx.x;
    int y2 = blockIdx.x * 32 + threadIdx.y;
    #pragma unroll
    for (int i = 0; i < 32; i += 8)
        AT[(size_t)(y2 + i) * D + x2] = tile[threadIdx.x][threadIdx.y + i];
}

__global__ void split_k(const float* __restrict__ s, __nv_bfloat16* __restrict__ h,
                        __nv_bfloat16* __restrict__ l, int n) {
    int i = blockIdx.x * blockDim.x + threadIdx.x;
    if (i >= n) return;
    float v = s[i];
    __nv_bfloat16 hv = __float2bfloat16(v);
    h[i] = hv;
    l[i] = __float2bfloat16(v - __bfloat162float(hv));
}

// ======================= HMMA (mma.sync) split-bf16 GEMM =======================
// C[m,n] = sum_k A[m,k]*B[n,k], fp32 accumulate.
// A, B supplied as bf16 (hi, lo) splits; C = Ah*Bh + Ah*Bl + Al*Bh.
// Block tile 128x128, 8 warps (2x4), warp tile 64x32, k-chunk 16, cp.async double buffer.
// Requires M, N % 128 == 0 and K % 16 == 0 (true for all call sites).
#define ROWB        48                    // bytes per smem tile row (16 bf16 + 8 pad)
#define TILE_BYTES  (128*ROWB)            // 6144
#define STAGE_BYTES (4*TILE_BYTES)        // 24576: Ah | Al | Bh | Bl
#define HG_SMEM     (2*STAGE_BYTES)       // 49152 (fits default dyn-smem limit)

__device__ __forceinline__ uint32_t smem_u32(const void* p) {
    uint32_t a;
    asm("{ .reg .u64 t; cvta.to.shared.u64 t, %1; cvt.u32.u64 %0, t; }" : "=r"(a) : "l"(p));
    return a;
}
__device__ __forceinline__ uint32_t lds32(uint32_t a) {
    uint32_t v;
    asm volatile("ld.shared.b32 %0, [%1];" : "=r"(v) : "r"(a));
    return v;
}
__device__ __forceinline__ void cp16(uint32_t dst, const void* src) {
    asm volatile("cp.async.cg.shared.global [%0], [%1], 16;" :: "r"(dst), "l"(src) : "memory");
}
__device__ __forceinline__ void cp_commit() {
    asm volatile("cp.async.commit_group;" ::: "memory");
}
template <int N>
__device__ __forceinline__ void cp_wait() {
    asm volatile("cp.async.wait_group %0;" :: "n"(N) : "memory");
}
__device__ __forceinline__ void mma16816(float* d, const uint32_t* a, const uint32_t* b) {
    asm volatile(
        "mma.sync.aligned.m16n8k16.row.col.f32.bf16.bf16.f32 "
        "{%0,%1,%2,%3}, {%4,%5,%6,%7}, {%8,%9}, {%0,%1,%2,%3};"
        : "+f"(d[0]), "+f"(d[1]), "+f"(d[2]), "+f"(d[3])
        : "r"(a[0]), "r"(a[1]), "r"(a[2]), "r"(a[3]), "r"(b[0]), "r"(b[1]));
}

__global__ __launch_bounds__(256, 2)
void hgemm(const __nv_bfloat16* __restrict__ Ah, const __nv_bfloat16* __restrict__ Al,
           const __nv_bfloat16* __restrict__ Bh, const __nv_bfloat16* __restrict__ Bl,
           float* __restrict__ C, int M, int N, int K) {
    extern __shared__ char smem[];
    const uint32_t sbase = smem_u32(smem);
    const int tid  = threadIdx.x;
    const int lane = tid & 31;
    const int wid  = tid >> 5;
    const int wr   = wid >> 2;          // 0..1 : 64-row slab
    const int wc   = wid & 3;           // 0..3 : 32-col slab
    const int mBase = blockIdx.y * 128;
    const int nBase = blockIdx.x * 128;

    // --- per-thread cp.async assignments: 4 x 16B segments per chunk ---
    const __nv_bfloat16* sp[4];
    uint32_t dof[4];
    #pragma unroll
    for (int i = 0; i < 4; i++) {
        int idx  = tid + i * 256;       // 0..1023
        int tile = idx >> 8;            // 0=Ah 1=Al 2=Bh 3=Bl
        int rem  = idx & 255;
        int row  = rem >> 1;
        int seg  = rem & 1;
        const __nv_bfloat16* base = (tile == 0) ? Ah : (tile == 1) ? Al : (tile == 2) ? Bh : Bl;
        int rbase = (tile < 2) ? mBase : nBase;
        sp[i]  = base + (size_t)(rbase + row) * K + seg * 8;
        dof[i] = (uint32_t)(tile * TILE_BYTES + row * ROWB + seg * 16);
    }

    float acc[4][4][4];
    #pragma unroll
    for (int mt = 0; mt < 4; mt++)
        #pragma unroll
        for (int nt = 0; nt < 4; nt++)
            #pragma unroll
            for (int j = 0; j < 4; j++) acc[mt][nt][j] = 0.f;

    const int nk = K >> 4;

    // prologue: chunk 0 -> stage 0
    #pragma unroll
    for (int i = 0; i < 4; i++) cp16(sbase + dof[i], sp[i]);
    cp_commit();

    const uint32_t rowAoff = (uint32_t)((wr * 64 + (lane >> 2)) * ROWB);
    const uint32_t rowBoff = (uint32_t)((wc * 32 + (lane >> 2)) * ROWB);
    const uint32_t colb    = (uint32_t)((lane & 3) * 4);

    for (int c = 0; c < nk; c++) {
        const int s = c & 1;
        if (c + 1 < nk) {
            const uint32_t so = sbase + (s ^ 1) * STAGE_BYTES;
            const int k1 = (c + 1) << 4;
            #pragma unroll
            for (int i = 0; i < 4; i++) cp16(so + dof[i], sp[i] + k1);
            cp_commit();
            cp_wait<1>();
        } else {
            cp_wait<0>();
        }
        __syncthreads();

        const uint32_t so = sbase + s * STAGE_BYTES;
        // 3 split passes: (Ah,Bh), (Ah,Bl), (Al,Bh)
        const uint32_t pA[3] = {0u, 0u, (uint32_t)TILE_BYTES};
        const uint32_t pB[3] = {(uint32_t)(2 * TILE_BYTES), (uint32_t)(3 * TILE_BYTES),
                                (uint32_t)(2 * TILE_BYTES)};
        #pragma unroll
        for (int p = 0; p < 3; p++) {
            const uint32_t ab = so + pA[p] + rowAoff + colb;
            const uint32_t bb = so + pB[p] + rowBoff + colb;
            uint32_t a[4][4], b[4][2];
            #pragma unroll
            for (int mt = 0; mt < 4; mt++) {
                uint32_t a0 = ab + (uint32_t)(mt * 16 * ROWB);
                a[mt][0] = lds32(a0);
                a[mt][1] = lds32(a0 + 8 * ROWB);
                a[mt][2] = lds32(a0 + 16);
                a[mt][3] = lds32(a0 + 8 * ROWB + 16);
            }
            #pragma unroll
            for (int nt = 0; nt < 4; nt++) {
                uint32_t b0 = bb + (uint32_t)(nt * 8 * ROWB);
                b[nt][0] = lds32(b0);
                b[nt][1] = lds32(b0 + 16);
            }
            #pragma unroll
            for (int mt = 0; mt < 4; mt++)
                #pragma unroll
                for (int nt = 0; nt < 4; nt++)
                    mma16816(acc[mt][nt], a[mt], b[nt]);
        }
        __syncthreads();
    }

    // epilogue
    const int row0 = mBase + wr * 64 + (lane >> 2);
    const int col0 = nBase + wc * 32 + (lane & 3) * 2;
    #pragma unroll
    for (int mt = 0; mt < 4; mt++) {
        #pragma unroll
        for (int nt = 0; nt < 4; nt++) {
            int r = row0 + mt * 16;
            int cc2 = col0 + nt * 8;
            *reinterpret_cast<float2*>(C + (size_t)r * N + cc2) =
                make_float2(acc[mt][nt][0], acc[mt][nt][1]);
            *reinterpret_cast<float2*>(C + (size_t)(r + 8) * N + cc2) =
                make_float2(acc[mt][nt][2], acc[mt][nt][3]);
        }
    }
}

// ======================= scan kernels =======================
__global__ __launch_bounds__(FP) void scan_partial(const int* __restrict__ perms) {
    __shared__ float skr[F], ski[F];
    const int b = blockIdx.y, ch = blockIdx.x;
    const int tid = threadIdx.x;
    const int f = tid;
    int   g[CC];
    float ar[CC], ai[CC];
    if (f < F) {
        #pragma unroll
        for (int c = 0; c < CC; c++) { g[c] = perms[c * F + f]; ar[c] = 0.f; ai[c] = 0.f; }
    }
    const int t0 = ch * CL;
    for (int t = t0; t < t0 + CL; t++) {
        const size_t row = (size_t)(b * TT + t) * N2;
        for (int i = tid; i < F; i += blockDim.x) {
            skr[i] = g_FK[row + i];
            ski[i] = g_FK[row + FP + i];
        }
        __syncthreads();
        if (f < F) {
            float vr = g_FV[row + f], vi = g_FV[row + FP + f];
            #pragma unroll
            for (int c = 0; c < CC; c++) {
                float kr = skr[g[c]], ki = ski[g[c]];
                ar[c] = fmaf(kr, vr, fmaf(-ki, vi, ar[c]));
                ai[c] = fmaf(kr, vi, fmaf( ki, vr, ai[c]));
            }
        }
        __syncthreads();
    }
    if (f < F) {
        size_t base = (size_t)(b * NCH + ch) * CC * FP + f;
        #pragma unroll
        for (int c = 0; c < CC; c++) {
            g_Sre[base + (size_t)c * FP] = ar[c];
            g_Sim[base + (size_t)c * FP] = ai[c];
        }
    }
}

__global__ void scan_offsets() {
    int idx = blockIdx.x * blockDim.x + threadIdx.x;
    if (idx >= BB * CC * FP) return;
    int f = idx % FP;
    int c = (idx / FP) % CC;
    int b = idx / (FP * CC);
    float rr = 0.f, ri = 0.f;
    for (int ch = 0; ch < NCH; ch++) {
        size_t off = ((size_t)(b * NCH + ch) * CC + c) * FP + f;
        float vr = g_Sre[off], vi = g_Sim[off];
        g_Sre[off] = rr; g_Sim[off] = ri;
        rr += vr; ri += vi;
    }
}

__global__ __launch_bounds__(FP) void scan_final(const int* __restrict__ perms) {
    __shared__ float skr[F], ski[F], sqr[F], sqi[F];
    const int b = blockIdx.y, ch = blockIdx.x;
    const int tid = threadIdx.x;
    const int f = tid;
    int   g[CC];
    float ar[CC], ai[CC];
    float s = 0.f;
    if (f < F) {
        size_t base = (size_t)(b * NCH + ch) * CC * FP + f;
        #pragma unroll
        for (int c = 0; c < CC; c++) {
            g[c]  = perms[c * F + f];
            ar[c] = g_Sre[base + (size_t)c * FP];
            ai[c] = g_Sim[base + (size_t)c * FP];
        }
        s = ((f == 0 || f == F - 1) ? 1.f : 2.f) / ((float)CC * (float)D);
    }
    const int t0 = ch * CL;
    for (int t = t0; t < t0 + CL; t++) {
        const size_t row = (size_t)(b * TT + t) * N2;
        for (int i = tid; i < F; i += blockDim.x) {
            skr[i] = g_FK[row + i];
            ski[i] = g_FK[row + FP + i];
            sqr[i] = g_FQ[row + i];
            sqi[i] = g_FQ[row + FP + i];
        }
        __syncthreads();
        if (f < F) {
            float vr = g_FV[row + f], vi = g_FV[row + FP + f];
            float rr = 0.f, ri = 0.f;
            #pragma unroll
            for (int c = 0; c < CC; c++) {
                float kr = skr[g[c]], ki = ski[g[c]];
                ar[c] = fmaf(kr, vr, fmaf(-ki, vi, ar[c]));
                ai[c] = fmaf(kr, vi, fmaf( ki, vr, ai[c]));
                float qr = sqr[g[c]], qi = sqi[g[c]];
                rr = fmaf(qr, ar[c], fmaf( qi, ai[c], rr));
                ri = fmaf(qr, ai[c], fmaf(-qi, ar[c], ri));
            }
            g_RS[row + f]      = rr * s;
            g_RS[row + FP + f] = ri * s;
        } else {
            g_RS[row + f]      = 0.f;
            g_RS[row + FP + f] = 0.f;
        }
        __syncthreads();
    }
}

// ======================= host launcher =======================
extern "C" void kernel_launch(void* const* d_in, const int* in_sizes, int n_in,
                              void* d_out, int out_size) {
    (void)in_sizes; (void)n_in; (void)out_size;
    const float* x     = (const float*)d_in[0];
    const float* Wq    = (const float*)d_in[1];
    const float* Wk    = (const float*)d_in[2];
    const float* Wv    = (const float*)d_in[3];
    const float* Wo    = (const float*)d_in[4];
    const int*   perms = (const int*)  d_in[5];
    float* out = (float*)d_out;

    float *pTW, *pWT0, *pWT1, *pWT2, *pWF0, *pWF1, *pWF2, *pGt, *pRS;
    __nv_bfloat16 *pTWh, *pTWl, *pW0h, *pW0l, *pW1h, *pW1l, *pW2h, *pW2l, *pWoh, *pWol;
    __nv_bfloat16 *pF0h, *pF0l, *pF1h, *pF1l, *pF2h, *pF2l, *pGth, *pGtl, *pXh, *pXl, *pRh, *pRl;
    float *pFQ, *pFK, *pFV;
    cudaGetSymbolAddress((void**)&pTW,  g_TW);
    cudaGetSymbolAddress((void**)&pWT0, g_WT0);
    cudaGetSymbolAddress((void**)&pWT1, g_WT1);
    cudaGetSymbolAddress((void**)&pWT2, g_WT2);
    cudaGetSymbolAddress((void**)&pWF0, g_WF0);
    cudaGetSymbolAddress((void**)&pWF1, g_WF1);
    cudaGetSymbolAddress((void**)&pWF2, g_WF2);
    cudaGetSymbolAddress((void**)&pGt,  g_Gt);
    cudaGetSymbolAddress((void**)&pRS,  g_RS);
    cudaGetSymbolAddress((void**)&pFQ,  g_FQ);
    cudaGetSymbolAddress((void**)&pFK,  g_FK);
    cudaGetSymbolAddress((void**)&pFV,  g_FV);
    cudaGetSymbolAddress((void**)&pTWh, g_TWh); cudaGetSymbolAddress((void**)&pTWl, g_TWl);
    cudaGetSymbolAddress((void**)&pW0h, g_W0h); cudaGetSymbolAddress((void**)&pW0l, g_W0l);
    cudaGetSymbolAddress((void**)&pW1h, g_W1h); cudaGetSymbolAddress((void**)&pW1l, g_W1l);
    cudaGetSymbolAddress((void**)&pW2h, g_W2h); cudaGetSymbolAddress((void**)&pW2l, g_W2l);
    cudaGetSymbolAddress((void**)&pWoh, g_Woh); cudaGetSymbolAddress((void**)&pWol, g_Wol);
    cudaGetSymbolAddress((void**)&pF0h, g_F0h); cudaGetSymbolAddress((void**)&pF0l, g_F0l);
    cudaGetSymbolAddress((void**)&pF1h, g_F1h); cudaGetSymbolAddress((void**)&pF1l, g_F1l);
    cudaGetSymbolAddress((void**)&pF2h, g_F2h); cudaGetSymbolAddress((void**)&pF2l, g_F2l);
    cudaGetSymbolAddress((void**)&pGth, g_Gth); cudaGetSymbolAddress((void**)&pGtl, g_Gtl);
    cudaGetSymbolAddress((void**)&pXh,  g_Xh);  cudaGetSymbolAddress((void**)&pXl,  g_Xl);
    cudaGetSymbolAddress((void**)&pRh,  g_Rh);  cudaGetSymbolAddress((void**)&pRl,  g_Rl);

    const int DD = D * D, TWN = N2 * D, XN = M4 * D, RN = M4 * N2;

    // 1. twiddles + weight transposes
    build_tw<<<dim3(D / 256, N2), 256>>>();
    transpose_k<<<dim3(32, 32), dim3(32, 8)>>>(Wq, pWT0);
    transpose_k<<<dim3(32, 32), dim3(32, 8)>>>(Wk, pWT1);
    transpose_k<<<dim3(32, 32), dim3(32, 8)>>>(Wv, pWT2);

    // 2. bf16 splits for weight-prep GEMMs
    split_k<<<(TWN + 255) / 256, 256>>>(pTW, pTWh, pTWl, TWN);
    split_k<<<(DD + 255) / 256, 256>>>(pWT0, pW0h, pW0l, DD);
    split_k<<<(DD + 255) / 256, 256>>>(pWT1, pW1h, pW1l, DD);
    split_k<<<(DD + 255) / 256, 256>>>(pWT2, pW2h, pW2l, DD);
    split_k<<<(DD + 255) / 256, 256>>>(Wo,   pWoh, pWol, DD);

    // 3. fused DFT weights: WF_i = NT(TW[N2,D], WT_i[D,D]) -> [N2, D]
    hgemm<<<dim3(8, 9), 256, HG_SMEM>>>(pTWh, pTWl, pW0h, pW0l, pWF0, N2, D, D);
    hgemm<<<dim3(8, 9), 256, HG_SMEM>>>(pTWh, pTWl, pW1h, pW1l, pWF1, N2, D, D);
    hgemm<<<dim3(8, 9), 256, HG_SMEM>>>(pTWh, pTWl, pW2h, pW2l, pWF2, N2, D, D);
    // 4. output-side weights: Gt = NT(Wo[D,D], TW[N2,D]) -> [D, N2]
    hgemm<<<dim3(9, 8), 256, HG_SMEM>>>(pWoh, pWol, pTWh, pTWl, pGt, D, N2, D);

    // 5. splits for the big GEMMs
    split_k<<<(XN + 255) / 256, 256>>>(x, pXh, pXl, XN);
    split_k<<<(TWN + 255) / 256, 256>>>(pWF0, pF0h, pF0l, TWN);
    split_k<<<(TWN + 255) / 256, 256>>>(pWF1, pF1h, pF1l, TWN);
    split_k<<<(TWN + 255) / 256, 256>>>(pWF2, pF2h, pF2l, TWN);
    split_k<<<(TWN + 255) / 256, 256>>>(pGt,  pGth, pGtl, TWN);

    // 6. projections fused with rfft: f* = NT(x[M4,D], WF[N2,D]) -> [M4, N2]
    hgemm<<<dim3(9, 32), 256, HG_SMEM>>>(pXh, pXl, pF0h, pF0l, pFQ, M4, N2, D);
    hgemm<<<dim3(9, 32), 256, HG_SMEM>>>(pXh, pXl, pF1h, pF1l, pFK, M4, N2, D);
    hgemm<<<dim3(9, 32), 256, HG_SMEM>>>(pXh, pXl, pF2h, pF2l, pFV, M4, N2, D);

    // 7. causal cumulative bind/unbind (chunked scan over T)
    scan_partial<<<dim3(NCH, BB), FP>>>(perms);
    scan_offsets<<<(BB * CC * FP + 255) / 256, 256>>>();
    scan_final  <<<dim3(NCH, BB), FP>>>(perms);

    // 8. irfft + output projection: out = NT(RS[M4,N2], Gt[D,N2]) -> [M4, D]
    split_k<<<(RN + 255) / 256, 256>>>(pRS, pRh, pRl, RN);
    hgemm<<<dim3(8, 32), 256, HG_SMEM>>>(pRh, pRl, pGth, pGtl, out, M4, D, N2);
}

// round 5
// speedup vs baseline: 2.0205x; 1.1091x over previous
#include <cuda_runtime.h>
#include <cuda_bf16.h>
#include <math.h>
#include <stdint.h>

// Problem constants
#define D    1024
#define F    513          // rfft bins
#define FP   576          // padded F (N2 = 1152 = 9*128; every GEMM dim % 128 == 0)
#define N2   (2*FP)       // 1152: [0..F) = re, [FP..FP+F) = im, pads zero
#define BB   2
#define TT   2048
#define M4   (BB*TT)      // 4096
#define CC   10
#define NCH  64
#define CL   (TT/NCH)     // 32

// ======================= static device scratch =======================
__device__ float g_TW [(size_t)N2*D];
__device__ float g_WT0[(size_t)D*D];
__device__ float g_WT1[(size_t)D*D];
__device__ float g_WT2[(size_t)D*D];
__device__ float g_WF0[(size_t)N2*D];
__device__ float g_WF1[(size_t)N2*D];
__device__ float g_WF2[(size_t)N2*D];
__device__ float g_Gt [(size_t)D*N2];
__device__ float g_FQ [(size_t)M4*N2];
__device__ float g_FK [(size_t)M4*N2];
__device__ float g_FV [(size_t)M4*N2];
__device__ float g_Sre[(size_t)BB*NCH*CC*FP];
__device__ float g_Sim[(size_t)BB*NCH*CC*FP];
// bf16 split buffers (hi, lo)
__device__ __nv_bfloat16 g_TWh[(size_t)N2*D],  g_TWl[(size_t)N2*D];
__device__ __nv_bfloat16 g_W0h[(size_t)D*D],   g_W0l[(size_t)D*D];
__device__ __nv_bfloat16 g_W1h[(size_t)D*D],   g_W1l[(size_t)D*D];
__device__ __nv_bfloat16 g_W2h[(size_t)D*D],   g_W2l[(size_t)D*D];
__device__ __nv_bfloat16 g_Woh[(size_t)D*D],   g_Wol[(size_t)D*D];
__device__ __nv_bfloat16 g_F0h[(size_t)N2*D],  g_F0l[(size_t)N2*D];
__device__ __nv_bfloat16 g_F1h[(size_t)N2*D],  g_F1l[(size_t)N2*D];
__device__ __nv_bfloat16 g_F2h[(size_t)N2*D],  g_F2l[(size_t)N2*D];
__device__ __nv_bfloat16 g_Gth[(size_t)D*N2],  g_Gtl[(size_t)D*N2];
__device__ __nv_bfloat16 g_Xh [(size_t)M4*D],  g_Xl [(size_t)M4*D];
__device__ __nv_bfloat16 g_Rh [(size_t)M4*N2], g_Rl [(size_t)M4*N2];

// ======================= small kernels =======================
__global__ void build_tw() {
    int d = blockIdx.x * blockDim.x + threadIdx.x;
    int n = blockIdx.y;
    if (d >= D) return;
    int f = (n < FP) ? n : n - FP;
    float v = 0.f;
    if (f < F) {
        int idx = (f * d) & (D - 1);
        double ang = (double)idx * (6.283185307179586476925286766559 / (double)D);
        v = (n < FP) ? (float)cos(ang) : (float)(-sin(ang));
    }
    g_TW[(size_t)n * D + d] = v;
}

__global__ void transpose_k(const float* __restrict__ A, float* __restrict__ AT) {
    __shared__ float tile[32][33];
    int x  = blockIdx.x * 32 + threadIdx.x;
    int y0 = blockIdx.y * 32 + threadIdx.y;
    #pragma unroll
    for (int i = 0; i < 32; i += 8)
        tile[threadIdx.y + i][threadIdx.x] = A[(size_t)(y0 + i) * D + x];
    __syncthreads();
    int x2 = blockIdx.y * 32 + threadIdx.x;
    int y2 = blockIdx.x * 32 + threadIdx.y;
    #pragma unroll
    for (int i = 0; i < 32; i += 8)
        AT[(size_t)(y2 + i) * D + x2] = tile[threadIdx.x][threadIdx.y + i];
}

__global__ void split_k(const float* __restrict__ s, __nv_bfloat16* __restrict__ h,
                        __nv_bfloat16* __restrict__ l, int n) {
    int i = blockIdx.x * blockDim.x + threadIdx.x;
    if (i >= n) return;
    float v = s[i];
    __nv_bfloat16 hv = __float2bfloat16(v);
    h[i] = hv;
    l[i] = __float2bfloat16(v - __bfloat162float(hv));
}

// ======================= HMMA (mma.sync) split-bf16 GEMM =======================
// C[m,n] = sum_k A[m,k]*B[n,k], fp32 accumulate; C = Ah*Bh + Ah*Bl + Al*Bh.
// Block tile 128x128, 8 warps (2x4), warp tile 64x32, k-chunk 16,
// 3-stage cp.async ring, one __syncthreads per chunk, ldmatrix fragment loads.
// Requires M, N % 128 == 0 and K % 16 == 0 (true at all call sites).
#define ROWB        48                    // bytes per smem tile row (16 bf16 + 8 pad)
#define TILE_BYTES  (128*ROWB)            // 6144
#define STAGE_BYTES (4*TILE_BYTES)        // 24576: Ah | Al | Bh | Bl
#define NSTAGE      3
#define HG_SMEM     (NSTAGE*STAGE_BYTES)  // 73728

__device__ __forceinline__ uint32_t smem_u32(const void* p) {
    uint32_t a;
    asm("{ .reg .u64 t; cvta.to.shared.u64 t, %1; cvt.u32.u64 %0, t; }" : "=r"(a) : "l"(p));
    return a;
}
__device__ __forceinline__ void cp16(uint32_t dst, const void* src) {
    asm volatile("cp.async.cg.shared.global [%0], [%1], 16;" :: "r"(dst), "l"(src) : "memory");
}
__device__ __forceinline__ void cp_commit() {
    asm volatile("cp.async.commit_group;" ::: "memory");
}
template <int N>
__device__ __forceinline__ void cp_wait() {
    asm volatile("cp.async.wait_group %0;" :: "n"(N) : "memory");
}
__device__ __forceinline__ void ldm4(uint32_t* r, uint32_t addr) {
    asm volatile("ldmatrix.sync.aligned.m8n8.x4.shared.b16 {%0,%1,%2,%3}, [%4];"
        : "=r"(r[0]), "=r"(r[1]), "=r"(r[2]), "=r"(r[3]) : "r"(addr));
}
__device__ __forceinline__ void mma16816(float* d, const uint32_t* a, const uint32_t* b) {
    asm volatile(
        "mma.sync.aligned.m16n8k16.row.col.f32.bf16.bf16.f32 "
        "{%0,%1,%2,%3}, {%4,%5,%6,%7}, {%8,%9}, {%0,%1,%2,%3};"
        : "+f"(d[0]), "+f"(d[1]), "+f"(d[2]), "+f"(d[3])
        : "r"(a[0]), "r"(a[1]), "r"(a[2]), "r"(a[3]), "r"(b[0]), "r"(b[1]));
}

__global__ __launch_bounds__(256, 2)
void hgemm(const __nv_bfloat16* __restrict__ Ah, const __nv_bfloat16* __restrict__ Al,
           const __nv_bfloat16* __restrict__ Bh, const __nv_bfloat16* __restrict__ Bl,
           float* __restrict__ C, int M, int N, int K) {
    extern __shared__ char smem[];
    const uint32_t sbase = smem_u32(smem);
    const int tid  = threadIdx.x;
    const int lane = tid & 31;
    const int wid  = tid >> 5;
    const int wr   = wid >> 2;          // 0..1 : 64-row slab
    const int wc   = wid & 3;           // 0..3 : 32-col slab
    const int mBase = blockIdx.y * 128;
    const int nBase = blockIdx.x * 128;

    // --- per-thread cp.async assignments: 4 x 16B segments per chunk ---
    const __nv_bfloat16* sp[4];
    uint32_t dof[4];
    #pragma unroll
    for (int i = 0; i < 4; i++) {
        int idx  = tid + i * 256;       // 0..1023
        int tile = idx >> 8;            // 0=Ah 1=Al 2=Bh 3=Bl
        int rem  = idx & 255;
        int row  = rem >> 1;
        int seg  = rem & 1;
        const __nv_bfloat16* base = (tile == 0) ? Ah : (tile == 1) ? Al : (tile == 2) ? Bh : Bl;
        int rbase = (tile < 2) ? mBase : nBase;
        sp[i]  = base + (size_t)(rbase + row) * K + seg * 8;
        dof[i] = (uint32_t)(tile * TILE_BYTES + row * ROWB + seg * 16);
    }

    float acc[4][4][4];
    #pragma unroll
    for (int mt = 0; mt < 4; mt++)
        #pragma unroll
        for (int nt = 0; nt < 4; nt++)
            #pragma unroll
            for (int j = 0; j < 4; j++) acc[mt][nt][j] = 0.f;

    const int nk = K >> 4;

    // prologue: chunks 0,1 -> stages 0,1
    #pragma unroll
    for (int i = 0; i < 4; i++) cp16(sbase + dof[i], sp[i]);
    cp_commit();
    #pragma unroll
    for (int i = 0; i < 4; i++) cp16(sbase + STAGE_BYTES + dof[i], sp[i] + 16);
    cp_commit();

    // ldmatrix per-lane intra-tile offsets
    const uint32_t aoff = sbase + (uint32_t)(wr * 64 * ROWB)
                        + (uint32_t)((lane & 15) * ROWB + (lane >> 4) * 16);
    const uint32_t boff = sbase + (uint32_t)(2 * TILE_BYTES + wc * 32 * ROWB)
                        + (uint32_t)((lane & 7) * ROWB + ((lane >> 3) & 1) * 16
                                     + (lane >> 4) * 8 * ROWB);
    // split passes: (Ah,Bh), (Ah,Bl), (Al,Bh)  [offsets within a stage]
    const uint32_t pA[3] = {0u, 0u, (uint32_t)TILE_BYTES};
    const uint32_t pB[3] = {0u, (uint32_t)TILE_BYTES, 0u};

    for (int c = 0; c < nk; c++) {
        cp_wait<1>();
        __syncthreads();
        // prefetch chunk c+2 into stage (c+2)%3 (frees stage consumed at c-1)
        if (c + 2 < nk) {
            const uint32_t so = sbase + ((c + 2) % NSTAGE) * STAGE_BYTES;
            const int k2 = (c + 2) << 4;
            #pragma unroll
            for (int i = 0; i < 4; i++) cp16(so + dof[i], sp[i] + k2);
        }
        cp_commit();

        const uint32_t st = ((uint32_t)(c % NSTAGE)) * STAGE_BYTES;
        #pragma unroll
        for (int p = 0; p < 3; p++) {
            uint32_t a[4][4], b[2][4];
            const uint32_t ab = aoff + st + pA[p];
            const uint32_t bb = boff + st + pB[p];
            #pragma unroll
            for (int mt = 0; mt < 4; mt++)
                ldm4(a[mt], ab + (uint32_t)(mt * 16 * ROWB));
            #pragma unroll
            for (int q = 0; q < 2; q++)
                ldm4(b[q], bb + (uint32_t)(q * 16 * ROWB));
            #pragma unroll
            for (int mt = 0; mt < 4; mt++)
                #pragma unroll
                for (int nt = 0; nt < 4; nt++)
                    mma16816(acc[mt][nt], a[mt], &b[nt >> 1][(nt & 1) * 2]);
        }
    }

    // epilogue
    const int row0 = mBase + wr * 64 + (lane >> 2);
    const int col0 = nBase + wc * 32 + (lane & 3) * 2;
    #pragma unroll
    for (int mt = 0; mt < 4; mt++) {
        #pragma unroll
        for (int nt = 0; nt < 4; nt++) {
            int r = row0 + mt * 16;
            int cc2 = col0 + nt * 8;
            *reinterpret_cast<float2*>(C + (size_t)r * N + cc2) =
                make_float2(acc[mt][nt][0], acc[mt][nt][1]);
            *reinterpret_cast<float2*>(C + (size_t)(r + 8) * N + cc2) =
                make_float2(acc[mt][nt][2], acc[mt][nt][3]);
        }
    }
}

// ======================= scan kernels =======================
__global__ __launch_bounds__(FP) void scan_partial(const int* __restrict__ perms) {
    __shared__ float skr[F], ski[F];
    const int b = blockIdx.y, ch = blockIdx.x;
    const int tid = threadIdx.x;
    const int f = tid;
    int   g[CC];
    float ar[CC], ai[CC];
    if (f < F) {
        #pragma unroll
        for (int c = 0; c < CC; c++) { g[c] = perms[c * F + f]; ar[c] = 0.f; ai[c] = 0.f; }
    }
    const int t0 = ch * CL;
    for (int t = t0; t < t0 + CL; t++) {
        const size_t row = (size_t)(b * TT + t) * N2;
        for (int i = tid; i < F; i += blockDim.x) {
            skr[i] = g_FK[row + i];
            ski[i] = g_FK[row + FP + i];
        }
        __syncthreads();
        if (f < F) {
            float vr = g_FV[row + f], vi = g_FV[row + FP + f];
            #pragma unroll
            for (int c = 0; c < CC; c++) {
                float kr = skr[g[c]], ki = ski[g[c]];
                ar[c] = fmaf(kr, vr, fmaf(-ki, vi, ar[c]));
                ai[c] = fmaf(kr, vi, fmaf( ki, vr, ai[c]));
            }
        }
        __syncthreads();
    }
    if (f < F) {
        size_t base = (size_t)(b * NCH + ch) * CC * FP + f;
        #pragma unroll
        for (int c = 0; c < CC; c++) {
            g_Sre[base + (size_t)c * FP] = ar[c];
            g_Sim[base + (size_t)c * FP] = ai[c];
        }
    }
}

__global__ void scan_offsets() {
    int idx = blockIdx.x * blockDim.x + threadIdx.x;
    if (idx >= BB * CC * FP) return;
    int f = idx % FP;
    int c = (idx / FP) % CC;
    int b = idx / (FP * CC);
    float rr = 0.f, ri = 0.f;
    for (int ch = 0; ch < NCH; ch++) {
        size_t off = ((size_t)(b * NCH + ch) * CC + c) * FP + f;
        float vr = g_Sre[off], vi = g_Sim[off];
        g_Sre[off] = rr; g_Sim[off] = ri;
        rr += vr; ri += vi;
    }
}

__global__ __launch_bounds__(FP) void scan_final(const int* __restrict__ perms) {
    __shared__ float skr[F], ski[F], sqr[F], sqi[F];
    const int b = blockIdx.y, ch = blockIdx.x;
    const int tid = threadIdx.x;
    const int f = tid;
    int   g[CC];
    float ar[CC], ai[CC];
    float s = 0.f;
    if (f < F) {
        size_t base = (size_t)(b * NCH + ch) * CC * FP + f;
        #pragma unroll
        for (int c = 0; c < CC; c++) {
            g[c]  = perms[c * F + f];
            ar[c] = g_Sre[base + (size_t)c * FP];
            ai[c] = g_Sim[base + (size_t)c * FP];
        }
        s = ((f == 0 || f == F - 1) ? 1.f : 2.f) / ((float)CC * (float)D);
    }
    const int t0 = ch * CL;
    for (int t = t0; t < t0 + CL; t++) {
        const size_t row = (size_t)(b * TT + t) * N2;
        for (int i = tid; i < F; i += blockDim.x) {
            skr[i] = g_FK[row + i];
            ski[i] = g_FK[row + FP + i];
            sqr[i] = g_FQ[row + i];
            sqi[i] = g_FQ[row + FP + i];
        }
        __syncthreads();
        if (f < F) {
            float vr = g_FV[row + f], vi = g_FV[row + FP + f];
            float rr = 0.f, ri = 0.f;
            #pragma unroll
            for (int c = 0; c < CC; c++) {
                float kr = skr[g[c]], ki = ski[g[c]];
                ar[c] = fmaf(kr, vr, fmaf(-ki, vi, ar[c]));
                ai[c] = fmaf(kr, vi, fmaf( ki, vr, ai[c]));
                float qr = sqr[g[c]], qi = sqi[g[c]];
                rr = fmaf(qr, ar[c], fmaf( qi, ai[c], rr));
                ri = fmaf(qr, ai[c], fmaf(-qi, ar[c], ri));
            }
            // fused bf16 hi/lo split of r * s
            float vRe = rr * s, vIm = ri * s;
            __nv_bfloat16 hRe = __float2bfloat16(vRe);
            __nv_bfloat16 hIm = __float2bfloat16(vIm);
            g_Rh[row + f]      = hRe;
            g_Rl[row + f]      = __float2bfloat16(vRe - __bfloat162float(hRe));
            g_Rh[row + FP + f] = hIm;
            g_Rl[row + FP + f] = __float2bfloat16(vIm - __bfloat162float(hIm));
        } else {
            __nv_bfloat16 z = __float2bfloat16(0.f);
            g_Rh[row + f]      = z; g_Rl[row + f]      = z;
            g_Rh[row + FP + f] = z; g_Rl[row + FP + f] = z;
        }
        __syncthreads();
    }
}

// ======================= host launcher =======================
extern "C" void kernel_launch(void* const* d_in, const int* in_sizes, int n_in,
                              void* d_out, int out_size) {
    (void)in_sizes; (void)n_in; (void)out_size;
    const float* x     = (const float*)d_in[0];
    const float* Wq    = (const float*)d_in[1];
    const float* Wk    = (const float*)d_in[2];
    const float* Wv    = (const float*)d_in[3];
    const float* Wo    = (const float*)d_in[4];
    const int*   perms = (const int*)  d_in[5];
    float* out = (float*)d_out;

    // non-stream host API; legal under graph capture, idempotent
    cudaFuncSetAttribute(hgemm, cudaFuncAttributeMaxDynamicSharedMemorySize, HG_SMEM);

    float *pTW, *pWT0, *pWT1, *pWT2, *pWF0, *pWF1, *pWF2, *pGt;
    __nv_bfloat16 *pTWh, *pTWl, *pW0h, *pW0l, *pW1h, *pW1l, *pW2h, *pW2l, *pWoh, *pWol;
    __nv_bfloat16 *pF0h, *pF0l, *pF1h, *pF1l, *pF2h, *pF2l, *pGth, *pGtl, *pXh, *pXl, *pRh, *pRl;
    float *pFQ, *pFK, *pFV;
    cudaGetSymbolAddress((void**)&pTW,  g_TW);
    cudaGetSymbolAddress((void**)&pWT0, g_WT0);
    cudaGetSymbolAddress((void**)&pWT1, g_WT1);
    cudaGetSymbolAddress((void**)&pWT2, g_WT2);
    cudaGetSymbolAddress((void**)&pWF0, g_WF0);
    cudaGetSymbolAddress((void**)&pWF1, g_WF1);
    cudaGetSymbolAddress((void**)&pWF2, g_WF2);
    cudaGetSymbolAddress((void**)&pGt,  g_Gt);
    cudaGetSymbolAddress((void**)&pFQ,  g_FQ);
    cudaGetSymbolAddress((void**)&pFK,  g_FK);
    cudaGetSymbolAddress((void**)&pFV,  g_FV);
    cudaGetSymbolAddress((void**)&pTWh, g_TWh); cudaGetSymbolAddress((void**)&pTWl, g_TWl);
    cudaGetSymbolAddress((void**)&pW0h, g_W0h); cudaGetSymbolAddress((void**)&pW0l, g_W0l);
    cudaGetSymbolAddress((void**)&pW1h, g_W1h); cudaGetSymbolAddress((void**)&pW1l, g_W1l);
    cudaGetSymbolAddress((void**)&pW2h, g_W2h); cudaGetSymbolAddress((void**)&pW2l, g_W2l);
    cudaGetSymbolAddress((void**)&pWoh, g_Woh); cudaGetSymbolAddress((void**)&pWol, g_Wol);
    cudaGetSymbolAddress((void**)&pF0h, g_F0h); cudaGetSymbolAddress((void**)&pF0l, g_F0l);
    cudaGetSymbolAddress((void**)&pF1h, g_F1h); cudaGetSymbolAddress((void**)&pF1l, g_F1l);
    cudaGetSymbolAddress((void**)&pF2h, g_F2h); cudaGetSymbolAddress((void**)&pF2l, g_F2l);
    cudaGetSymbolAddress((void**)&pGth, g_Gth); cudaGetSymbolAddress((void**)&pGtl, g_Gtl);
    cudaGetSymbolAddress((void**)&pXh,  g_Xh);  cudaGetSymbolAddress((void**)&pXl,  g_Xl);
    cudaGetSymbolAddress((void**)&pRh,  g_Rh);  cudaGetSymbolAddress((void**)&pRl,  g_Rl);

    const int DD = D * D, TWN = N2 * D, XN = M4 * D;

    // 1. twiddles + weight transposes
    build_tw<<<dim3(D / 256, N2), 256>>>();
    transpose_k<<<dim3(32, 32), dim3(32, 8)>>>(Wq, pWT0);
    transpose_k<<<dim3(32, 32), dim3(32, 8)>>>(Wk, pWT1);
    transpose_k<<<dim3(32, 32), dim3(32, 8)>>>(Wv, pWT2);

    // 2. bf16 splits for weight-prep GEMMs
    split_k<<<(TWN + 255) / 256, 256>>>(pTW, pTWh, pTWl, TWN);
    split_k<<<(DD + 255) / 256, 256>>>(pWT0, pW0h, pW0l, DD);
    split_k<<<(DD + 255) / 256, 256>>>(pWT1, pW1h, pW1l, DD);
    split_k<<<(DD + 255) / 256, 256>>>(pWT2, pW2h, pW2l, DD);
    split_k<<<(DD + 255) / 256, 256>>>(Wo,   pWoh, pWol, DD);

    // 3. fused DFT weights: WF_i = NT(TW[N2,D], WT_i[D,D]) -> [N2, D]
    hgemm<<<dim3(8, 9), 256, HG_SMEM>>>(pTWh, pTWl, pW0h, pW0l, pWF0, N2, D, D);
    hgemm<<<dim3(8, 9), 256, HG_SMEM>>>(pTWh, pTWl, pW1h, pW1l, pWF1, N2, D, D);
    hgemm<<<dim3(8, 9), 256, HG_SMEM>>>(pTWh, pTWl, pW2h, pW2l, pWF2, N2, D, D);
    // 4. output-side weights: Gt = NT(Wo[D,D], TW[N2,D]) -> [D, N2]
    hgemm<<<dim3(9, 8), 256, HG_SMEM>>>(pWoh, pWol, pTWh, pTWl, pGt, D, N2, D);

    // 5. splits for the big GEMMs
    split_k<<<(XN + 255) / 256, 256>>>(x, pXh, pXl, XN);
    split_k<<<(TWN + 255) / 256, 256>>>(pWF0, pF0h, pF0l, TWN);
    split_k<<<(TWN + 255) / 256, 256>>>(pWF1, pF1h, pF1l, TWN);
    split_k<<<(TWN + 255) / 256, 256>>>(pWF2, pF2h, pF2l, TWN);
    split_k<<<(TWN + 255) / 256, 256>>>(pGt,  pGth, pGtl, TWN);

    // 6. projections fused with rfft: f* = NT(x[M4,D], WF[N2,D]) -> [M4, N2]
    hgemm<<<dim3(9, 32), 256, HG_SMEM>>>(pXh, pXl, pF0h, pF0l, pFQ, M4, N2, D);
    hgemm<<<dim3(9, 32), 256, HG_SMEM>>>(pXh, pXl, pF1h, pF1l, pFK, M4, N2, D);
    hgemm<<<dim3(9, 32), 256, HG_SMEM>>>(pXh, pXl, pF2h, pF2l, pFV, M4, N2, D);

    // 7. causal cumulative bind/unbind (chunked scan over T); scan_final
    //    writes the bf16 hi/lo split of r directly (no fp32 round trip)
    scan_partial<<<dim3(NCH, BB), FP>>>(perms);
    scan_offsets<<<(BB * CC * FP + 255) / 256, 256>>>();
    scan_final  <<<dim3(NCH, BB), FP>>>(perms);

    // 8. irfft + output projection: out = NT(R[M4,N2], Gt[D,N2]) -> [M4, D]
    hgemm<<<dim3(8, 32), 256, HG_SMEM>>>(pRh, pRl, pGth, pGtl, out, M4, D, N2);
}

// round 9
// speedup vs baseline: 2.4199x; 1.1977x over previous
#include <cuda_runtime.h>
#include <cuda_bf16.h>
#include <math.h>
#include <stdint.h>

// Problem constants
#define D    1024
#define F    513          // rfft bins
#define FP   576          // padded F (N2 = 1152 = 9*128; every GEMM dim % 128 == 0)
#define N2   (2*FP)       // 1152: [0..F) = re, [FP..FP+F) = im, pads zero
#define BB   2
#define TT   2048
#define M4   (BB*TT)      // 4096
#define CC   10
#define NCH  64
#define CL   (TT/NCH)     // 32

#define DDSZ   ((size_t)D*D)
#define TWNSZ  ((size_t)N2*D)
#define XNSZ   ((size_t)M4*D)
#define FPLANE ((size_t)M4*N2)

// ======================= static device scratch =======================
__device__ float g_TW  [TWNSZ];           // fp32 twiddles
__device__ float g_WTc [3*DDSZ];          // Wq^T | Wk^T | Wv^T
__device__ float g_F3  [3*FPLANE];        // fq | fk | fv planes (fp32)
__device__ float g_Sre [(size_t)BB*NCH*CC*FP];
__device__ float g_Sim [(size_t)BB*NCH*CC*FP];
// bf16 hi/lo pairs
__device__ __nv_bfloat16 g_TWh[TWNSZ],   g_TWl[TWNSZ];
__device__ __nv_bfloat16 g_WTh[3*DDSZ],  g_WTl[3*DDSZ];
__device__ __nv_bfloat16 g_Woh[DDSZ],    g_Wol[DDSZ];
__device__ __nv_bfloat16 g_Xh [XNSZ],    g_Xl [XNSZ];
__device__ __nv_bfloat16 g_WFh[3*TWNSZ], g_WFl[3*TWNSZ];   // fused DFT weights (cat over q,k,v)
__device__ __nv_bfloat16 g_Gth[TWNSZ],   g_Gtl[TWNSZ];     // Wo @ TW^T
__device__ __nv_bfloat16 g_Rh [FPLANE],  g_Rl [FPLANE];

// ======================= small kernels =======================
__global__ void build_tw() {
    int d = blockIdx.x * blockDim.x + threadIdx.x;
    int n = blockIdx.y;
    if (d >= D) return;
    int f = (n < FP) ? n : n - FP;
    float v = 0.f;
    if (f < F) {
        int idx = (f * d) & (D - 1);                 // exact argument reduction
        float s, c;
        sincosf((float)idx * 6.135923151542565e-3f, &s, &c);  // 2*pi/1024
        v = (n < FP) ? c : -s;
    }
    g_TW[(size_t)n * D + d] = v;
}

__global__ void transpose3(const float* __restrict__ A0, const float* __restrict__ A1,
                           const float* __restrict__ A2) {
    __shared__ float tile[32][33];
    const float* A = (blockIdx.z == 0) ? A0 : (blockIdx.z == 1) ? A1 : A2;
    float* AT = g_WTc + (size_t)blockIdx.z * DDSZ;
    int x  = blockIdx.x * 32 + threadIdx.x;
    int y0 = blockIdx.y * 32 + threadIdx.y;
    #pragma unroll
    for (int i = 0; i < 32; i += 8)
        tile[threadIdx.y + i][threadIdx.x] = A[(size_t)(y0 + i) * D + x];
    __syncthreads();
    int x2 = blockIdx.y * 32 + threadIdx.x;
    int y2 = blockIdx.x * 32 + threadIdx.y;
    #pragma unroll
    for (int i = 0; i < 32; i += 8)
        AT[(size_t)(y2 + i) * D + x2] = tile[threadIdx.x][threadIdx.y + i];
}

// one launch: split TW, WTcat, Wo, x into bf16 hi/lo
__global__ void split_all(const float* __restrict__ Wo, const float* __restrict__ x) {
    size_t i = (size_t)blockIdx.x * blockDim.x + threadIdx.x;
    const float* src;
    __nv_bfloat16 *h, *l;
    size_t off;
    if (i < TWNSZ) {
        src = g_TW;  h = g_TWh; l = g_TWl; off = i;
    } else if (i < TWNSZ + 3*DDSZ) {
        src = g_WTc; h = g_WTh; l = g_WTl; off = i - TWNSZ;
    } else if (i < TWNSZ + 4*DDSZ) {
        src = Wo;    h = g_Woh; l = g_Wol; off = i - TWNSZ - 3*DDSZ;
    } else if (i < TWNSZ + 4*DDSZ + XNSZ) {
        src = x;     h = g_Xh;  l = g_Xl;  off = i - TWNSZ - 4*DDSZ;
    } else return;
    float v = src[off];
    __nv_bfloat16 hv = __float2bfloat16(v);
    h[off] = hv;
    l[off] = __float2bfloat16(v - __bfloat162float(hv));
}

// ======================= HMMA (mma.sync) split-bf16 GEMM =======================
// C[m,n] = sum_k A[m,k]*B[n,k], fp32 accumulate; C = Ah*Bh + Ah*Bl + Al*Bh.
// Block tile 128x128, 8 warps (2x4), warp tile 64x32, k-chunk 16,
// 3-stage cp.async ring, one __syncthreads per chunk, ldmatrix fragment loads.
// blockIdx.z advances A/B/C by aZ/bZ/cZ elements (merged batched calls).
// BF16OUT=1: write bf16 hi/lo split instead of fp32.
#define ROWB        48                    // bytes per smem tile row (16 bf16 + 8 pad)
#define TILE_BYTES  (128*ROWB)            // 6144
#define STAGE_BYTES (4*TILE_BYTES)        // 24576: Ah | Al | Bh | Bl
#define NSTAGE      3
#define HG_SMEM     (NSTAGE*STAGE_BYTES)  // 73728

__device__ __forceinline__ uint32_t smem_u32(const void* p) {
    uint32_t a;
    asm("{ .reg .u64 t; cvta.to.shared.u64 t, %1; cvt.u32.u64 %0, t; }" : "=r"(a) : "l"(p));
    return a;
}
__device__ __forceinline__ void cp16(uint32_t dst, const void* src) {
    asm volatile("cp.async.cg.shared.global [%0], [%1], 16;" :: "r"(dst), "l"(src) : "memory");
}
__device__ __forceinline__ void cp_commit() {
    asm volatile("cp.async.commit_group;" ::: "memory");
}
template <int N>
__device__ __forceinline__ void cp_wait() {
    asm volatile("cp.async.wait_group %0;" :: "n"(N) : "memory");
}
__device__ __forceinline__ void ldm4(uint32_t* r, uint32_t addr) {
    asm volatile("ldmatrix.sync.aligned.m8n8.x4.shared.b16 {%0,%1,%2,%3}, [%4];"
        : "=r"(r[0]), "=r"(r[1]), "=r"(r[2]), "=r"(r[3]) : "r"(addr));
}
__device__ __forceinline__ void mma16816(float* d, const uint32_t* a, const uint32_t* b) {
    asm volatile(
        "mma.sync.aligned.m16n8k16.row.col.f32.bf16.bf16.f32 "
        "{%0,%1,%2,%3}, {%4,%5,%6,%7}, {%8,%9}, {%0,%1,%2,%3};"
        : "+f"(d[0]), "+f"(d[1]), "+f"(d[2]), "+f"(d[3])
        : "r"(a[0]), "r"(a[1]), "r"(a[2]), "r"(a[3]), "r"(b[0]), "r"(b[1]));
}

template <int BF16OUT>
__global__ __launch_bounds__(256, 2)
void hgemm(const __nv_bfloat16* __restrict__ Ah, const __nv_bfloat16* __restrict__ Al,
           const __nv_bfloat16* __restrict__ Bh, const __nv_bfloat16* __restrict__ Bl,
           float* __restrict__ Cf, __nv_bfloat16* __restrict__ Ch, __nv_bfloat16* __restrict__ Cl,
           int M, int N, int K, size_t aZ, size_t bZ, size_t cZ) {
    extern __shared__ char smem[];
    const uint32_t sbase = smem_u32(smem);
    const int tid  = threadIdx.x;
    const int lane = tid & 31;
    const int wid  = tid >> 5;
    const int wr   = wid >> 2;          // 0..1 : 64-row slab
    const int wc   = wid & 3;           // 0..3 : 32-col slab
    const int mBase = blockIdx.y * 128;
    const int nBase = blockIdx.x * 128;
    const size_t zA = (size_t)blockIdx.z * aZ;
    const size_t zB = (size_t)blockIdx.z * bZ;
    Ah += zA; Al += zA; Bh += zB; Bl += zB;

    // --- per-thread cp.async assignments: 4 x 16B segments per chunk ---
    const __nv_bfloat16* sp[4];
    uint32_t dof[4];
    #pragma unroll
    for (int i = 0; i < 4; i++) {
        int idx  = tid + i * 256;       // 0..1023
        int tile = idx >> 8;            // 0=Ah 1=Al 2=Bh 3=Bl
        int rem  = idx & 255;
        int row  = rem >> 1;
        int seg  = rem & 1;
        const __nv_bfloat16* base = (tile == 0) ? Ah : (tile == 1) ? Al : (tile == 2) ? Bh : Bl;
        int rbase = (tile < 2) ? mBase : nBase;
        sp[i]  = base + (size_t)(rbase + row) * K + seg * 8;
        dof[i] = (uint32_t)(tile * TILE_BYTES + row * ROWB + seg * 16);
    }

    float acc[4][4][4];
    #pragma unroll
    for (int mt = 0; mt < 4; mt++)
        #pragma unroll
        for (int nt = 0; nt < 4; nt++)
            #pragma unroll
            for (int j = 0; j < 4; j++) acc[mt][nt][j] = 0.f;

    const int nk = K >> 4;

    // prologue: chunks 0,1 -> stages 0,1
    #pragma unroll
    for (int i = 0; i < 4; i++) cp16(sbase + dof[i], sp[i]);
    cp_commit();
    #pragma unroll
    for (int i = 0; i < 4; i++) cp16(sbase + STAGE_BYTES + dof[i], sp[i] + 16);
    cp_commit();

    // ldmatrix per-lane intra-tile offsets
    const uint32_t aoff = sbase + (uint32_t)(wr * 64 * ROWB)
                        + (uint32_t)((lane & 15) * ROWB + (lane >> 4) * 16);
    const uint32_t boff = sbase + (uint32_t)(2 * TILE_BYTES + wc * 32 * ROWB)
                        + (uint32_t)((lane & 7) * ROWB + ((lane >> 3) & 1) * 16
                                     + (lane >> 4) * 8 * ROWB);
    // split passes: (Ah,Bh), (Ah,Bl), (Al,Bh)  [offsets within a stage]
    const uint32_t pA[3] = {0u, 0u, (uint32_t)TILE_BYTES};
    const uint32_t pB[3] = {0u, (uint32_t)TILE_BYTES, 0u};

    for (int c = 0; c < nk; c++) {
        cp_wait<1>();
        __syncthreads();
        // prefetch chunk c+2 into stage (c+2)%3 (frees stage consumed at c-1)
        if (c + 2 < nk) {
            const uint32_t so = sbase + ((c + 2) % NSTAGE) * STAGE_BYTES;
            const int k2 = (c + 2) << 4;
            #pragma unroll
            for (int i = 0; i < 4; i++) cp16(so + dof[i], sp[i] + k2);
        }
        cp_commit();

        const uint32_t st = ((uint32_t)(c % NSTAGE)) * STAGE_BYTES;
        #pragma unroll
        for (int p = 0; p < 3; p++) {
            uint32_t a[4][4], b[2][4];
            const uint32_t ab = aoff + st + pA[p];
            const uint32_t bb = boff + st + pB[p];
            #pragma unroll
            for (int mt = 0; mt < 4; mt++)
                ldm4(a[mt], ab + (uint32_t)(mt * 16 * ROWB));
            #pragma unroll
            for (int q = 0; q < 2; q++)
                ldm4(b[q], bb + (uint32_t)(q * 16 * ROWB));
            #pragma unroll
            for (int mt = 0; mt < 4; mt++)
                #pragma unroll
                for (int nt = 0; nt < 4; nt++)
                    mma16816(acc[mt][nt], a[mt], &b[nt >> 1][(nt & 1) * 2]);
        }
    }

    // epilogue
    const int row0 = mBase + wr * 64 + (lane >> 2);
    const int col0 = nBase + wc * 32 + (lane & 3) * 2;
    const size_t zC = (size_t)blockIdx.z * cZ;
    #pragma unroll
    for (int mt = 0; mt < 4; mt++) {
        #pragma unroll
        for (int nt = 0; nt < 4; nt++) {
            int r = row0 + mt * 16;
            int cc2 = col0 + nt * 8;
            #pragma unroll
            for (int half = 0; half < 2; half++) {
                size_t pos = zC + (size_t)(r + half * 8) * N + cc2;
                float v0 = acc[mt][nt][half * 2 + 0];
                float v1 = acc[mt][nt][half * 2 + 1];
                if (BF16OUT) {
                    __nv_bfloat16 h0 = __float2bfloat16(v0);
                    __nv_bfloat16 h1 = __float2bfloat16(v1);
                    __nv_bfloat162 hp, lp;
                    hp.x = h0; hp.y = h1;
                    lp.x = __float2bfloat16(v0 - __bfloat162float(h0));
                    lp.y = __float2bfloat16(v1 - __bfloat162float(h1));
                    *reinterpret_cast<__nv_bfloat162*>(Ch + pos) = hp;
                    *reinterpret_cast<__nv_bfloat162*>(Cl + pos) = lp;
                } else {
                    *reinterpret_cast<float2*>(Cf + pos) = make_float2(v0, v1);
                }
            }
        }
    }
}

// ======================= scan kernels =======================
#define pFQ (g_F3)
#define pFKg (g_F3 + FPLANE)
#define pFVg (g_F3 + 2*FPLANE)

__global__ __launch_bounds__(FP) void scan_partial(const int* __restrict__ perms) {
    __shared__ float skr[F], ski[F];
    const int b = blockIdx.y, ch = blockIdx.x;
    const int tid = threadIdx.x;
    const int f = tid;
    int   g[CC];
    float ar[CC], ai[CC];
    if (f < F) {
        #pragma unroll
        for (int c = 0; c < CC; c++) { g[c] = perms[c * F + f]; ar[c] = 0.f; ai[c] = 0.f; }
    }
    const int t0 = ch * CL;
    for (int t = t0; t < t0 + CL; t++) {
        const size_t row = (size_t)(b * TT + t) * N2;
        for (int i = tid; i < F; i += blockDim.x) {
            skr[i] = pFKg[row + i];
            ski[i] = pFKg[row + FP + i];
        }
        __syncthreads();
        if (f < F) {
            float vr = pFVg[row + f], vi = pFVg[row + FP + f];
            #pragma unroll
            for (int c = 0; c < CC; c++) {
                float kr = skr[g[c]], ki = ski[g[c]];
                ar[c] = fmaf(kr, vr, fmaf(-ki, vi, ar[c]));
                ai[c] = fmaf(kr, vi, fmaf( ki, vr, ai[c]));
            }
        }
        __syncthreads();
    }
    if (f < F) {
        size_t base = (size_t)(b * NCH + ch) * CC * FP + f;
        #pragma unroll
        for (int c = 0; c < CC; c++) {
            g_Sre[base + (size_t)c * FP] = ar[c];
            g_Sim[base + (size_t)c * FP] = ai[c];
        }
    }
}

__global__ void scan_offsets() {
    int idx = blockIdx.x * blockDim.x + threadIdx.x;
    if (idx >= BB * CC * FP) return;
    int f = idx % FP;
    int c = (idx / FP) % CC;
    int b = idx / (FP * CC);
    float rr = 0.f, ri = 0.f;
    for (int ch = 0; ch < NCH; ch++) {
        size_t off = ((size_t)(b * NCH + ch) * CC + c) * FP + f;
        float vr = g_Sre[off], vi = g_Sim[off];
        g_Sre[off] = rr; g_Sim[off] = ri;
        rr += vr; ri += vi;
    }
}

__global__ __launch_bounds__(FP) void scan_final(const int* __restrict__ perms) {
    __shared__ float skr[F], ski[F], sqr[F], sqi[F];
    const int b = blockIdx.y, ch = blockIdx.x;
    const int tid = threadIdx.x;
    const int f = tid;
    int   g[CC];
    float ar[CC], ai[CC];
    float s = 0.f;
    if (f < F) {
        size_t base = (size_t)(b * NCH + ch) * CC * FP + f;
        #pragma unroll
        for (int c = 0; c < CC; c++) {
            g[c]  = perms[c * F + f];
            ar[c] = g_Sre[base + (size_t)c * FP];
            ai[c] = g_Sim[base + (size_t)c * FP];
        }
        s = ((f == 0 || f == F - 1) ? 1.f : 2.f) / ((float)CC * (float)D);
    }
    const int t0 = ch * CL;
    for (int t = t0; t < t0 + CL; t++) {
        const size_t row = (size_t)(b * TT + t) * N2;
        for (int i = tid; i < F; i += blockDim.x) {
            skr[i] = pFKg[row + i];
            ski[i] = pFKg[row + FP + i];
            sqr[i] = pFQ[row + i];
            sqi[i] = pFQ[row + FP + i];
        }
        __syncthreads();
        if (f < F) {
            float vr = pFVg[row + f], vi = pFVg[row + FP + f];
            float rr = 0.f, ri = 0.f;
            #pragma unroll
            for (int c = 0; c < CC; c++) {
                float kr = skr[g[c]], ki = ski[g[c]];
                ar[c] = fmaf(kr, vr, fmaf(-ki, vi, ar[c]));
                ai[c] = fmaf(kr, vi, fmaf( ki, vr, ai[c]));
                float qr = sqr[g[c]], qi = sqi[g[c]];
                rr = fmaf(qr, ar[c], fmaf( qi, ai[c], rr));
                ri = fmaf(qr, ai[c], fmaf(-qi, ar[c], ri));
            }
            float vRe = rr * s, vIm = ri * s;
            __nv_bfloat16 hRe = __float2bfloat16(vRe);
            __nv_bfloat16 hIm = __float2bfloat16(vIm);
            g_Rh[row + f]      = hRe;
            g_Rl[row + f]      = __float2bfloat16(vRe - __bfloat162float(hRe));
            g_Rh[row + FP + f] = hIm;
            g_Rl[row + FP + f] = __float2bfloat16(vIm - __bfloat162float(hIm));
        } else {
            __nv_bfloat16 z = __float2bfloat16(0.f);
            g_Rh[row + f]      = z; g_Rl[row + f]      = z;
            g_Rh[row + FP + f] = z; g_Rl[row + FP + f] = z;
        }
        __syncthreads();
    }
}

// ======================= host launcher =======================
extern "C" void kernel_launch(void* const* d_in, const int* in_sizes, int n_in,
                              void* d_out, int out_size) {
    (void)in_sizes; (void)n_in; (void)out_size;
    const float* x     = (const float*)d_in[0];
    const float* Wq    = (const float*)d_in[1];
    const float* Wk    = (const float*)d_in[2];
    const float* Wv    = (const float*)d_in[3];
    const float* Wo    = (const float*)d_in[4];
    const int*   perms = (const int*)  d_in[5];
    float* out = (float*)d_out;

    cudaFuncSetAttribute(hgemm<0>, cudaFuncAttributeMaxDynamicSharedMemorySize, HG_SMEM);
    cudaFuncSetAttribute(hgemm<1>, cudaFuncAttributeMaxDynamicSharedMemorySize, HG_SMEM);

    __nv_bfloat16 *pTWh, *pTWl, *pWTh, *pWTl, *pWoh, *pWol, *pXh, *pXl;
    __nv_bfloat16 *pWFh, *pWFl, *pGth, *pGtl, *pRh, *pRl;
    float *pF3;
    cudaGetSymbolAddress((void**)&pTWh, g_TWh); cudaGetSymbolAddress((void**)&pTWl, g_TWl);
    cudaGetSymbolAddress((void**)&pWTh, g_WTh); cudaGetSymbolAddress((void**)&pWTl, g_WTl);
    cudaGetSymbolAddress((void**)&pWoh, g_Woh); cudaGetSymbolAddress((void**)&pWol, g_Wol);
    cudaGetSymbolAddress((void**)&pXh,  g_Xh);  cudaGetSymbolAddress((void**)&pXl,  g_Xl);
    cudaGetSymbolAddress((void**)&pWFh, g_WFh); cudaGetSymbolAddress((void**)&pWFl, g_WFl);
    cudaGetSymbolAddress((void**)&pGth, g_Gth); cudaGetSymbolAddress((void**)&pGtl, g_Gtl);
    cudaGetSymbolAddress((void**)&pRh,  g_Rh);  cudaGetSymbolAddress((void**)&pRl,  g_Rl);
    cudaGetSymbolAddress((void**)&pF3,  g_F3);

    // 0: twiddles
    build_tw<<<dim3(D / 256, N2), 256>>>();
    // 1: all three weight transposes
    transpose3<<<dim3(32, 32, 3), dim3(32, 8)>>>(Wq, Wk, Wv);
    // 2: all bf16 splits (TW, WTcat, Wo, x)
    {
        size_t total = TWNSZ + 4*DDSZ + XNSZ;
        split_all<<<(unsigned)((total + 255) / 256), 256>>>(Wo, x);
    }
    // 3: fused DFT weights for q,k,v in one launch: WF_z = NT(TW, WT_z) -> bf16 h/l
    hgemm<1><<<dim3(8, 9, 3), 256, HG_SMEM>>>(pTWh, pTWl, pWTh, pWTl,
        nullptr, pWFh, pWFl, N2, D, D, 0, DDSZ, TWNSZ);
    // 4: output-side weights: Gt = NT(Wo, TW) -> bf16 h/l
    hgemm<1><<<dim3(9, 8, 1), 256, HG_SMEM>>>(pWoh, pWol, pTWh, pTWl,
        nullptr, pGth, pGtl, D, N2, D, 0, 0, 0);
    // 5: merged QKV projections+rfft: F3_z = NT(x, WF_z)  [the big one; profiled]
    hgemm<0><<<dim3(9, 32, 3), 256, HG_SMEM>>>(pXh, pXl, pWFh, pWFl,
        pF3, nullptr, nullptr, M4, N2, D, 0, TWNSZ, FPLANE);
    // 6-8: causal cumulative bind/unbind (chunked scan over T)
    scan_partial<<<dim3(NCH, BB), FP>>>(perms);
    scan_offsets<<<(BB * CC * FP + 255) / 256, 256>>>();
    scan_final  <<<dim3(NCH, BB), FP>>>(perms);
    // 9: irfft + output projection: out = NT(R, Gt)
    hgemm<0><<<dim3(8, 32, 1), 256, HG_SMEM>>>(pRh, pRl, pGth, pGtl,
        out, nullptr, nullptr, M4, D, N2, 0, 0, 0);
}

// round 11
// speedup vs baseline: 2.7748x; 1.1466x over previous
#include <cuda_runtime.h>
#include <cuda_bf16.h>
#include <math.h>
#include <stdint.h>

// Problem constants
#define D    1024
#define F    513          // rfft bins
#define FP   520          // padded F (mult of 8); N2 = 1040 (65 k16-chunks)
#define N2   (2*FP)       // 1040: [0..F) = re, [FP..FP+F) = im, pads zero
#define BB   2
#define TT   2048
#define M4   (BB*TT)      // 4096
#define CC   10
#define NCH  64
#define CL   (TT/NCH)     // 32

#define DDSZ   ((size_t)D*D)
#define TWNSZ  ((size_t)N2*D)
#define XNSZ   ((size_t)M4*D)
#define FPLANE ((size_t)M4*N2)

// ======================= static device scratch =======================
__device__ float g_WTc [3*DDSZ];          // Wq^T | Wk^T | Wv^T
__device__ float g_F3  [3*FPLANE];        // fq | fk | fv planes (fp32)
__device__ float g_Sre [(size_t)BB*NCH*CC*FP];
__device__ float g_Sim [(size_t)BB*NCH*CC*FP];
// bf16 hi/lo pairs
__device__ __nv_bfloat16 g_TWh[TWNSZ],   g_TWl[TWNSZ];     // twiddles (split at build)
__device__ __nv_bfloat16 g_WTh[3*DDSZ],  g_WTl[3*DDSZ];
__device__ __nv_bfloat16 g_Woh[DDSZ],    g_Wol[DDSZ];
__device__ __nv_bfloat16 g_Xh [XNSZ],    g_Xl [XNSZ];
__device__ __nv_bfloat16 g_WFh[3*TWNSZ], g_WFl[3*TWNSZ];   // fused DFT weights
__device__ __nv_bfloat16 g_Gth[TWNSZ],   g_Gtl[TWNSZ];     // Wo @ TW^T
__device__ __nv_bfloat16 g_Rh [FPLANE],  g_Rl [FPLANE];

// ======================= small kernels =======================
__global__ void build_tw() {
    int d = blockIdx.x * blockDim.x + threadIdx.x;
    int n = blockIdx.y;
    if (d >= D) return;
    int f = (n < FP) ? n : n - FP;
    float v = 0.f;
    if (f < F) {
        int idx = (f * d) & (D - 1);                 // exact argument reduction
        float s, c;
        sincosf((float)idx * 6.135923151542565e-3f, &s, &c);  // 2*pi/1024
        v = (n < FP) ? c : -s;
    }
    size_t o = (size_t)n * D + d;
    __nv_bfloat16 hv = __float2bfloat16(v);
    g_TWh[o] = hv;
    g_TWl[o] = __float2bfloat16(v - __bfloat162float(hv));
}

__global__ void transpose3(const float* __restrict__ A0, const float* __restrict__ A1,
                           const float* __restrict__ A2) {
    __shared__ float tile[32][33];
    const float* A = (blockIdx.z == 0) ? A0 : (blockIdx.z == 1) ? A1 : A2;
    float* AT = g_WTc + (size_t)blockIdx.z * DDSZ;
    int x  = blockIdx.x * 32 + threadIdx.x;
    int y0 = blockIdx.y * 32 + threadIdx.y;
    #pragma unroll
    for (int i = 0; i < 32; i += 8)
        tile[threadIdx.y + i][threadIdx.x] = A[(size_t)(y0 + i) * D + x];
    __syncthreads();
    int x2 = blockIdx.y * 32 + threadIdx.x;
    int y2 = blockIdx.x * 32 + threadIdx.y;
    #pragma unroll
    for (int i = 0; i < 32; i += 8)
        AT[(size_t)(y2 + i) * D + x2] = tile[threadIdx.x][threadIdx.y + i];
}

// one launch: split WTcat, Wo, x into bf16 hi/lo
__global__ void split_all(const float* __restrict__ Wo, const float* __restrict__ x) {
    size_t i = (size_t)blockIdx.x * blockDim.x + threadIdx.x;
    const float* src;
    __nv_bfloat16 *h, *l;
    size_t off;
    if (i < 3*DDSZ) {
        src = g_WTc; h = g_WTh; l = g_WTl; off = i;
    } else if (i < 4*DDSZ) {
        src = Wo;    h = g_Woh; l = g_Wol; off = i - 3*DDSZ;
    } else if (i < 4*DDSZ + XNSZ) {
        src = x;     h = g_Xh;  l = g_Xl;  off = i - 4*DDSZ;
    } else return;
    float v = src[off];
    __nv_bfloat16 hv = __float2bfloat16(v);
    h[off] = hv;
    l[off] = __float2bfloat16(v - __bfloat162float(hv));
}

// ======================= HMMA (mma.sync) split-bf16 GEMM =======================
// C[m,n] = sum_k A[m,k]*B[n,k], fp32 accumulate; C = Ah*Bh + Ah*Bl + Al*Bh.
// Block tile 128x128, 8 warps (2x4), warp tile 64x32, k-chunk 16,
// 3-stage cp.async ring, one __syncthreads per chunk, ldmatrix fragment loads.
// Handles ragged M/N tails via cp.async src-size zero-fill + predicated stores.
#define ROWB        48                    // bytes per smem tile row (16 bf16 + 8 pad)
#define TILE_BYTES  (128*ROWB)            // 6144
#define STAGE_BYTES (4*TILE_BYTES)        // 24576: Ah | Al | Bh | Bl
#define NSTAGE      3
#define HG_SMEM     (NSTAGE*STAGE_BYTES)  // 73728

__device__ __forceinline__ uint32_t smem_u32(const void* p) {
    uint32_t a;
    asm("{ .reg .u64 t; cvta.to.shared.u64 t, %1; cvt.u32.u64 %0, t; }" : "=r"(a) : "l"(p));
    return a;
}
__device__ __forceinline__ void cp16z(uint32_t dst, const void* src, uint32_t srcsz) {
    asm volatile("cp.async.cg.shared.global [%0], [%1], 16, %2;"
                 :: "r"(dst), "l"(src), "r"(srcsz) : "memory");
}
__device__ __forceinline__ void cp_commit() {
    asm volatile("cp.async.commit_group;" ::: "memory");
}
template <int N>
__device__ __forceinline__ void cp_wait() {
    asm volatile("cp.async.wait_group %0;" :: "n"(N) : "memory");
}
__device__ __forceinline__ void ldm4(uint32_t* r, uint32_t addr) {
    asm volatile("ldmatrix.sync.aligned.m8n8.x4.shared.b16 {%0,%1,%2,%3}, [%4];"
        : "=r"(r[0]), "=r"(r[1]), "=r"(r[2]), "=r"(r[3]) : "r"(addr));
}
__device__ __forceinline__ void mma16816(float* d, const uint32_t* a, const uint32_t* b) {
    asm volatile(
        "mma.sync.aligned.m16n8k16.row.col.f32.bf16.bf16.f32 "
        "{%0,%1,%2,%3}, {%4,%5,%6,%7}, {%8,%9}, {%0,%1,%2,%3};"
        : "+f"(d[0]), "+f"(d[1]), "+f"(d[2]), "+f"(d[3])
        : "r"(a[0]), "r"(a[1]), "r"(a[2]), "r"(a[3]), "r"(b[0]), "r"(b[1]));
}

template <int BF16OUT>
__device__ __forceinline__ void hgemm_core(
    const __nv_bfloat16* __restrict__ Ah, const __nv_bfloat16* __restrict__ Al,
    const __nv_bfloat16* __restrict__ Bh, const __nv_bfloat16* __restrict__ Bl,
    float* __restrict__ Cf, __nv_bfloat16* __restrict__ Ch, __nv_bfloat16* __restrict__ Cl,
    int M, int N, int K, int mBase, int nBase, char* smem) {
    const uint32_t sbase = smem_u32(smem);
    const int tid  = threadIdx.x;
    const int lane = tid & 31;
    const int wid  = tid >> 5;
    const int wr   = wid >> 2;          // 0..1 : 64-row slab
    const int wc   = wid & 3;           // 0..3 : 32-col slab

    // --- per-thread cp.async assignments: 4 x 16B segments per chunk ---
    const __nv_bfloat16* sp[4];
    uint32_t dof[4];
    uint32_t vmask = 0;
    #pragma unroll
    for (int i = 0; i < 4; i++) {
        int idx  = tid + i * 256;       // 0..1023
        int tile = idx >> 8;            // 0=Ah 1=Al 2=Bh 3=Bl
        int rem  = idx & 255;
        int row  = rem >> 1;
        int seg  = rem & 1;
        const __nv_bfloat16* base = (tile == 0) ? Ah : (tile == 1) ? Al : (tile == 2) ? Bh : Bl;
        int rowsTot = (tile < 2) ? M : N;
        int gr = ((tile < 2) ? mBase : nBase) + row;
        bool valid = gr < rowsTot;
        if (valid) vmask |= (1u << i);
        int cr = valid ? gr : (rowsTot - 1);
        sp[i]  = base + (size_t)cr * K + seg * 8;
        dof[i] = (uint32_t)(tile * TILE_BYTES + row * ROWB + seg * 16);
    }

    float acc[4][4][4];
    #pragma unroll
    for (int mt = 0; mt < 4; mt++)
        #pragma unroll
        for (int nt = 0; nt < 4; nt++)
            #pragma unroll
            for (int j = 0; j < 4; j++) acc[mt][nt][j] = 0.f;

    const int nk = K >> 4;

    // prologue: chunks 0,1 -> stages 0,1
    #pragma unroll
    for (int i = 0; i < 4; i++) cp16z(sbase + dof[i], sp[i], ((vmask >> i) & 1) << 4);
    cp_commit();
    #pragma unroll
    for (int i = 0; i < 4; i++) cp16z(sbase + STAGE_BYTES + dof[i], sp[i] + 16, ((vmask >> i) & 1) << 4);
    cp_commit();

    // ldmatrix per-lane intra-tile offsets
    const uint32_t aoff = sbase + (uint32_t)(wr * 64 * ROWB)
                        + (uint32_t)((lane & 15) * ROWB + (lane >> 4) * 16);
    const uint32_t boff = sbase + (uint32_t)(2 * TILE_BYTES + wc * 32 * ROWB)
                        + (uint32_t)((lane & 7) * ROWB + ((lane >> 3) & 1) * 16
                                     + (lane >> 4) * 8 * ROWB);
    // split passes: (Ah,Bh), (Ah,Bl), (Al,Bh)  [offsets within a stage]
    const uint32_t pA[3] = {0u, 0u, (uint32_t)TILE_BYTES};
    const uint32_t pB[3] = {0u, (uint32_t)TILE_BYTES, 0u};

    for (int c = 0; c < nk; c++) {
        cp_wait<1>();
        __syncthreads();
        // prefetch chunk c+2 into stage (c+2)%3 (frees stage consumed at c-1)
        if (c + 2 < nk) {
            const uint32_t so = sbase + ((c + 2) % NSTAGE) * STAGE_BYTES;
            const int k2 = (c + 2) << 4;
            #pragma unroll
            for (int i = 0; i < 4; i++)
                cp16z(so + dof[i], sp[i] + k2, ((vmask >> i) & 1) << 4);
        }
        cp_commit();

        const uint32_t st = ((uint32_t)(c % NSTAGE)) * STAGE_BYTES;
        #pragma unroll
        for (int p = 0; p < 3; p++) {
            uint32_t a[4][4], b[2][4];
            const uint32_t ab = aoff + st + pA[p];
            const uint32_t bb = boff + st + pB[p];
            #pragma unroll
            for (int mt = 0; mt < 4; mt++)
                ldm4(a[mt], ab + (uint32_t)(mt * 16 * ROWB));
            #pragma unroll
            for (int q = 0; q < 2; q++)
                ldm4(b[q], bb + (uint32_t)(q * 16 * ROWB));
            #pragma unroll
            for (int mt = 0; mt < 4; mt++)
                #pragma unroll
                for (int nt = 0; nt < 4; nt++)
                    mma16816(acc[mt][nt], a[mt], &b[nt >> 1][(nt & 1) * 2]);
        }
    }

    // epilogue (predicated for ragged M/N tails)
    const int row0 = mBase + wr * 64 + (lane >> 2);
    const int col0 = nBase + wc * 32 + (lane & 3) * 2;
    #pragma unroll
    for (int mt = 0; mt < 4; mt++) {
        #pragma unroll
        for (int nt = 0; nt < 4; nt++) {
            int cc2 = col0 + nt * 8;
            if (cc2 >= N) continue;
            #pragma unroll
            for (int half = 0; half < 2; half++) {
                int r = row0 + mt * 16 + half * 8;
                if (r >= M) continue;
                size_t pos = (size_t)r * N + cc2;
                float v0 = acc[mt][nt][half * 2 + 0];
                float v1 = acc[mt][nt][half * 2 + 1];
                if (BF16OUT) {
                    __nv_bfloat16 h0 = __float2bfloat16(v0);
                    __nv_bfloat16 h1 = __float2bfloat16(v1);
                    __nv_bfloat162 hp, lp;
                    hp.x = h0; hp.y = h1;
                    lp.x = __float2bfloat16(v0 - __bfloat162float(h0));
                    lp.y = __float2bfloat16(v1 - __bfloat162float(h1));
                    *reinterpret_cast<__nv_bfloat162*>(Ch + pos) = hp;
                    *reinterpret_cast<__nv_bfloat162*>(Cl + pos) = lp;
                } else {
                    *reinterpret_cast<float2*>(Cf + pos) = make_float2(v0, v1);
                }
            }
        }
    }
}

// big GEMMs (fp32 out): z batches A/B/C by aZ/bZ/cZ elements
__global__ __launch_bounds__(256, 2)
void hgemm_main(const __nv_bfloat16* __restrict__ Ah, const __nv_bfloat16* __restrict__ Al,
                const __nv_bfloat16* __restrict__ Bh, const __nv_bfloat16* __restrict__ Bl,
                float* __restrict__ Cf, int M, int N, int K,
                size_t aZ, size_t bZ, size_t cZ) {
    extern __shared__ char smem[];
    const size_t zA = (size_t)blockIdx.z * aZ;
    const size_t zB = (size_t)blockIdx.z * bZ;
    hgemm_core<0>(Ah + zA, Al + zA, Bh + zB, Bl + zB,
                  Cf + (size_t)blockIdx.z * cZ, nullptr, nullptr,
                  M, N, K, blockIdx.y * 128, blockIdx.x * 128, smem);
}

// weight-prep GEMMs (bf16 h/l out), all four in one launch:
//   z<3 : WF_z[N2,D] = NT(TW[N2,D], WT_z[D,D])
//   z=3 : Gt[D,N2]   = NT(Wo[D,D],  TW[N2,D])
__global__ __launch_bounds__(256, 2)
void hgemm_prep() {
    extern __shared__ char smem[];
    const int z = blockIdx.z;
    const __nv_bfloat16 *Ah, *Al, *Bh, *Bl;
    __nv_bfloat16 *Ch, *Cl;
    int M, N;
    if (z < 3) {
        M = N2; N = D;
        Ah = g_TWh; Al = g_TWl;
        Bh = g_WTh + (size_t)z * DDSZ; Bl = g_WTl + (size_t)z * DDSZ;
        Ch = g_WFh + (size_t)z * TWNSZ; Cl = g_WFl + (size_t)z * TWNSZ;
    } else {
        M = D; N = N2;
        Ah = g_Woh; Al = g_Wol;
        Bh = g_TWh; Bl = g_TWl;
        Ch = g_Gth; Cl = g_Gtl;
    }
    const int mBase = blockIdx.y * 128;
    const int nBase = blockIdx.x * 128;
    if (mBase >= M || nBase >= N) return;
    hgemm_core<1>(Ah, Al, Bh, Bl, nullptr, Ch, Cl, M, N, D, mBase, nBase, smem);
}

// ======================= scan kernels =======================
#define pFQ (g_F3)
#define pFKg (g_F3 + FPLANE)
#define pFVg (g_F3 + 2*FPLANE)

__global__ __launch_bounds__(FP) void scan_partial(const int* __restrict__ perms) {
    __shared__ float skr[F], ski[F];
    const int b = blockIdx.y, ch = blockIdx.x;
    const int tid = threadIdx.x;
    const int f = tid;
    int   g[CC];
    float ar[CC], ai[CC];
    if (f < F) {
        #pragma unroll
        for (int c = 0; c < CC; c++) { g[c] = perms[c * F + f]; ar[c] = 0.f; ai[c] = 0.f; }
    }
    const int t0 = ch * CL;
    for (int t = t0; t < t0 + CL; t++) {
        const size_t row = (size_t)(b * TT + t) * N2;
        for (int i = tid; i < F; i += blockDim.x) {
            skr[i] = pFKg[row + i];
            ski[i] = pFKg[row + FP + i];
        }
        __syncthreads();
        if (f < F) {
            float vr = pFVg[row + f], vi = pFVg[row + FP + f];
            #pragma unroll
            for (int c = 0; c < CC; c++) {
                float kr = skr[g[c]], ki = ski[g[c]];
                ar[c] = fmaf(kr, vr, fmaf(-ki, vi, ar[c]));
                ai[c] = fmaf(kr, vi, fmaf( ki, vr, ai[c]));
            }
        }
        __syncthreads();
    }
    if (f < F) {
        size_t base = (size_t)(b * NCH + ch) * CC * FP + f;
        #pragma unroll
        for (int c = 0; c < CC; c++) {
            g_Sre[base + (size_t)c * FP] = ar[c];
            g_Sim[base + (size_t)c * FP] = ai[c];
        }
    }
}

__global__ void scan_offsets() {
    int idx = blockIdx.x * blockDim.x + threadIdx.x;
    if (idx >= BB * CC * FP) return;
    int f = idx % FP;
    int c = (idx / FP) % CC;
    int b = idx / (FP * CC);
    float rr = 0.f, ri = 0.f;
    for (int ch = 0; ch < NCH; ch++) {
        size_t off = ((size_t)(b * NCH + ch) * CC + c) * FP + f;
        float vr = g_Sre[off], vi = g_Sim[off];
        g_Sre[off] = rr; g_Sim[off] = ri;
        rr += vr; ri += vi;
    }
}

__global__ __launch_bounds__(FP) void scan_final(const int* __restrict__ perms) {
    __shared__ float skr[F], ski[F], sqr[F], sqi[F];
    const int b = blockIdx.y, ch = blockIdx.x;
    const int tid = threadIdx.x;
    const int f = tid;
    int   g[CC];
    float ar[CC], ai[CC];
    float s = 0.f;
    if (f < F) {
        size_t base = (size_t)(b * NCH + ch) * CC * FP + f;
        #pragma unroll
        for (int c = 0; c < CC; c++) {
            g[c]  = perms[c * F + f];
            ar[c] = g_Sre[base + (size_t)c * FP];
            ai[c] = g_Sim[base + (size_t)c * FP];
        }
        s = ((f == 0 || f == F - 1) ? 1.f : 2.f) / ((float)CC * (float)D);
    }
    const int t0 = ch * CL;
    for (int t = t0; t < t0 + CL; t++) {
        const size_t row = (size_t)(b * TT + t) * N2;
        for (int i = tid; i < F; i += blockDim.x) {
            skr[i] = pFKg[row + i];
            ski[i] = pFKg[row + FP + i];
            sqr[i] = pFQ[row + i];
            sqi[i] = pFQ[row + FP + i];
        }
        __syncthreads();
        if (f < F) {
            float vr = pFVg[row + f], vi = pFVg[row + FP + f];
            float rr = 0.f, ri = 0.f;
            #pragma unroll
            for (int c = 0; c < CC; c++) {
                float kr = skr[g[c]], ki = ski[g[c]];
                ar[c] = fmaf(kr, vr, fmaf(-ki, vi, ar[c]));
                ai[c] = fmaf(kr, vi, fmaf( ki, vr, ai[c]));
                float qr = sqr[g[c]], qi = sqi[g[c]];
                rr = fmaf(qr, ar[c], fmaf( qi, ai[c], rr));
                ri = fmaf(qr, ai[c], fmaf(-qi, ar[c], ri));
            }
            float vRe = rr * s, vIm = ri * s;
            __nv_bfloat16 hRe = __float2bfloat16(vRe);
            __nv_bfloat16 hIm = __float2bfloat16(vIm);
            g_Rh[row + f]      = hRe;
            g_Rl[row + f]      = __float2bfloat16(vRe - __bfloat162float(hRe));
            g_Rh[row + FP + f] = hIm;
            g_Rl[row + FP + f] = __float2bfloat16(vIm - __bfloat162float(hIm));
        } else {
            __nv_bfloat16 z = __float2bfloat16(0.f);
            g_Rh[row + f]      = z; g_Rl[row + f]      = z;
            g_Rh[row + FP + f] = z; g_Rl[row + FP + f] = z;
        }
        __syncthreads();
    }
}

// ======================= host launcher =======================
extern "C" void kernel_launch(void* const* d_in, const int* in_sizes, int n_in,
                              void* d_out, int out_size) {
    (void)in_sizes; (void)n_in; (void)out_size;
    const float* x     = (const float*)d_in[0];
    const float* Wq    = (const float*)d_in[1];
    const float* Wk    = (const float*)d_in[2];
    const float* Wv    = (const float*)d_in[3];
    const float* Wo    = (const float*)d_in[4];
    const int*   perms = (const int*)  d_in[5];
    float* out = (float*)d_out;

    cudaFuncSetAttribute(hgemm_main, cudaFuncAttributeMaxDynamicSharedMemorySize, HG_SMEM);
    cudaFuncSetAttribute(hgemm_prep, cudaFuncAttributeMaxDynamicSharedMemorySize, HG_SMEM);

    __nv_bfloat16 *pXh, *pXl, *pWFh, *pWFl, *pGth, *pGtl, *pRh, *pRl;
    float *pF3;
    cudaGetSymbolAddress((void**)&pXh,  g_Xh);  cudaGetSymbolAddress((void**)&pXl,  g_Xl);
    cudaGetSymbolAddress((void**)&pWFh, g_WFh); cudaGetSymbolAddress((void**)&pWFl, g_WFl);
    cudaGetSymbolAddress((void**)&pGth, g_Gth); cudaGetSymbolAddress((void**)&pGtl, g_Gtl);
    cudaGetSymbolAddress((void**)&pRh,  g_Rh);  cudaGetSymbolAddress((void**)&pRl,  g_Rl);
    cudaGetSymbolAddress((void**)&pF3,  g_F3);

    // 0: twiddles (bf16 split written directly)
    build_tw<<<dim3(D / 256, N2), 256>>>();
    // 1: all three weight transposes
    transpose3<<<dim3(32, 32, 3), dim3(32, 8)>>>(Wq, Wk, Wv);
    // 2: bf16 splits (WTcat, Wo, x)
    {
        size_t total = 4*DDSZ + XNSZ;
        split_all<<<(unsigned)((total + 255) / 256), 256>>>(Wo, x);
    }
    // 3: all four weight-prep GEMMs in one launch (WF q,k,v + Gt)
    hgemm_prep<<<dim3(9, 9, 4), 256, HG_SMEM>>>();
    // 4: merged QKV projections+rfft: F3_z = NT(x, WF_z)
    hgemm_main<<<dim3(9, 32, 3), 256, HG_SMEM>>>(pXh, pXl, pWFh, pWFl,
        pF3, M4, N2, D, 0, TWNSZ, FPLANE);
    // 5-7: causal cumulative bind/unbind (chunked scan over T)
    scan_partial<<<dim3(NCH, BB), FP>>>(perms);
    scan_offsets<<<(BB * CC * FP + 255) / 256, 256>>>();
    scan_final  <<<dim3(NCH, BB), FP>>>(perms);
    // 8: irfft + output projection: out = NT(R, Gt)
    hgemm_main<<<dim3(8, 32, 1), 256, HG_SMEM>>>(pRh, pRl, pGth, pGtl,
        out, M4, D, N2, 0, 0, 0);
}